// round 7
// baseline (speedup 1.0000x reference)
#include <cuda_runtime.h>
#include <cuda_bf16.h>
#include <cstdint>

#define NN   50000
#define EE   800000
#define DINN 128
#define DHH  256
#define DOUTT 64
#define GGG  64
#define TOTE (EE + NN)
#define NCHUNK 49   // ceil(NN/1024)

// ---------------- scratch (static device globals) ---------------------------
__device__ __align__(16) float g_h[(size_t)NN * DHH];   // GEMM output (per layer)
__device__ __align__(16) float g_f[(size_t)NN * DHH];   // aggregated features
__device__ __align__(16) __nv_bfloat16 g_ah[(size_t)NN * DHH];
__device__ __align__(16) __nv_bfloat16 g_al[(size_t)NN * DHH];
__device__ __align__(16) __nv_bfloat16 g_bh[DHH * DHH];   // Wt hi [256][K]
__device__ __align__(16) __nv_bfloat16 g_bl[DHH * DHH];   // Wt lo [256][K]
__device__ float g_sv[NN];
__device__ float g_dv[NN];
__device__ float g_pool[GGG * DHH];
__device__ int   g_cnt[NN];
__device__ int   g_rowptr[NN + 1];
__device__ int   g_cur[NN];
__device__ int   g_col[TOTE];
__device__ int   g_csum[NCHUNK];
__device__ int   g_i32;      // 1 => index tensors are int32, 0 => int64

// ---------------- dtype-agnostic index load ---------------------------------
__device__ __forceinline__ int ld_idx(const void* p, long i) {
    return g_i32 ? ((const int*)p)[i] : (int)((const long long*)p)[i];
}

__global__ void k_detect(const int* __restrict__ ei32) {
    __shared__ int any;
    if (threadIdx.x == 0) any = 0;
    __syncthreads();
    if (ei32[2 * threadIdx.x + 1] != 0) atomicOr(&any, 1);
    __syncthreads();
    if (threadIdx.x == 0) g_i32 = any;
}

// ---------------- CSR build -------------------------------------------------
__global__ void k_init_cnt() {
    int i = blockIdx.x * blockDim.x + threadIdx.x;
    if (i < NN) g_cnt[i] = 1;   // self-loop
}

__global__ void k_hist(const void* __restrict__ ei) {
    int e = blockIdx.x * blockDim.x + threadIdx.x;
    if (e < EE) atomicAdd(&g_cnt[ld_idx(ei, (long)EE + e)], 1);
}

__global__ void k_chunk_sum() {
    __shared__ int sr[1024];
    int tid = threadIdx.x;
    int i = blockIdx.x * 1024 + tid;
    sr[tid] = (i < NN) ? g_cnt[i] : 0;
    __syncthreads();
    for (int off = 512; off; off >>= 1) {
        if (tid < off) sr[tid] += sr[tid + off];
        __syncthreads();
    }
    if (tid == 0) g_csum[blockIdx.x] = sr[0];
}

__global__ void k_scan_chunks() {
    int run = 0;
    for (int c = 0; c < NCHUNK; c++) {
        int t = g_csum[c];
        g_csum[c] = run;
        run += t;
    }
    g_rowptr[NN] = TOTE;
}

__global__ void k_local_scan() {
    __shared__ int ss[1024];
    int tid = threadIdx.x;
    int i = blockIdx.x * 1024 + tid;
    int v = (i < NN) ? g_cnt[i] : 0;
    ss[tid] = v;
    __syncthreads();
    for (int off = 1; off < 1024; off <<= 1) {
        int add = (tid >= off) ? ss[tid - off] : 0;
        __syncthreads();
        ss[tid] += add;
        __syncthreads();
    }
    if (i < NN) {
        int rp = g_csum[blockIdx.x] + ss[tid] - v;   // exclusive
        g_rowptr[i] = rp;
        g_cur[i] = rp;
    }
}

__global__ void k_scatter(const void* __restrict__ ei) {
    int idx = blockIdx.x * blockDim.x + threadIdx.x;
    if (idx < GGG * DHH) g_pool[idx] = 0.f;     // fold pool zeroing in
    if (idx < EE) {
        int src = ld_idx(ei, idx);
        int dst = ld_idx(ei, (long)EE + idx);
        int pos = atomicAdd(&g_cur[dst], 1);
        g_col[pos] = src;
    } else if (idx < TOTE) {
        int i = idx - EE;
        int pos = atomicAdd(&g_cur[i], 1);
        g_col[pos] = i;
    }
}

// ---------------- fp32 -> bf16 hi/lo conversion (layer-1 input only) --------
__global__ void k_cvt_a(const float4* __restrict__ A, int n4) {
    int i = blockIdx.x * blockDim.x + threadIdx.x;
    if (i >= n4) return;
    float4 v = A[i];
    __nv_bfloat16 hx = __float2bfloat16_rn(v.x);
    __nv_bfloat16 hy = __float2bfloat16_rn(v.y);
    __nv_bfloat16 hz = __float2bfloat16_rn(v.z);
    __nv_bfloat16 hw = __float2bfloat16_rn(v.w);
    __nv_bfloat162* oh = (__nv_bfloat162*)g_ah;
    __nv_bfloat162* ol = (__nv_bfloat162*)g_al;
    oh[2 * i]     = __nv_bfloat162(hx, hy);
    oh[2 * i + 1] = __nv_bfloat162(hz, hw);
    ol[2 * i]     = __nv_bfloat162(__float2bfloat16_rn(v.x - __bfloat162float(hx)),
                                   __float2bfloat16_rn(v.y - __bfloat162float(hy)));
    ol[2 * i + 1] = __nv_bfloat162(__float2bfloat16_rn(v.z - __bfloat162float(hz)),
                                   __float2bfloat16_rn(v.w - __bfloat162float(hw)));
}

// W [K, 256] fp32 -> Wt_hi/Wt_lo [256, K] bf16 (transposed, K contiguous).
// Also zeroes g_sv/g_dv for the fused-epilogue atomics of the following GEMM.
__global__ void k_cvt_w(const float* __restrict__ W, int K) {
    int i = blockIdx.x * blockDim.x + threadIdx.x;
    if (i < NN) { g_sv[i] = 0.f; g_dv[i] = 0.f; }
    if (i >= K * DHH) return;
    int n = i / K, k = i - n * K;
    float f = W[(size_t)k * DHH + n];
    __nv_bfloat16 h = __float2bfloat16_rn(f);
    g_bh[i] = h;
    g_bl[i] = __float2bfloat16_rn(f - __bfloat162float(h));
}

// ---------------- HMMA bf16 GEMM: C[M,256] = A[M,K] @ Wt^T ------------------
// mma.sync m16n8k16 bf16, hi/lo 3-pass split. Fused epilogue also accumulates
// s_i = h_i . a_src and d_i = h_i . a_dst via quad-reduce + atomicAdd.
__device__ __forceinline__ void mma16816(float* c, const uint32_t* a, uint32_t b0, uint32_t b1) {
    asm volatile("mma.sync.aligned.m16n8k16.row.col.f32.bf16.bf16.f32 "
                 "{%0,%1,%2,%3}, {%4,%5,%6,%7}, {%8,%9}, {%0,%1,%2,%3};"
                 : "+f"(c[0]), "+f"(c[1]), "+f"(c[2]), "+f"(c[3])
                 : "r"(a[0]), "r"(a[1]), "r"(a[2]), "r"(a[3]), "r"(b0), "r"(b1));
}

#define ASTR 80   // A row stride bytes (32 bf16 + 8 pad)

__global__ __launch_bounds__(256) void k_gemm_mma(
    const __nv_bfloat16* __restrict__ Ah, const __nv_bfloat16* __restrict__ Al,
    const __nv_bfloat16* __restrict__ Bh, const __nv_bfloat16* __restrict__ Bl,
    float* __restrict__ C, const float* __restrict__ asrc, const float* __restrict__ adst,
    int M, int K)
{
    extern __shared__ char smem[];
    const int BSTR = 2 * K + 16;            // B row stride bytes (odd multiple of 16)
    char* sAh = smem;                       // 128 * 80 = 10240
    char* sAl = smem + 10240;               // 10240
    char* sBh = smem + 20480;               // 64 * BSTR
    char* sBl = sBh + 64 * BSTR;
    float* sAv = (float*)(sBl + 64 * BSTR); // asrc copy [256]
    float* sDv = sAv + DHH;                 // adst copy [256]

    int tid = threadIdx.x;
    int wid = tid >> 5, lane = tid & 31;
    int warp_m = wid >> 1, warp_n = wid & 1;
    int group = lane >> 2, tq = lane & 3;
    int m0 = blockIdx.y * 128;
    int n0 = blockIdx.x * 64;

    sAv[tid] = asrc[tid];
    sDv[tid] = adst[tid];

    // ---- load B slice (64 rows x K, hi+lo) once ----
    {
        int kc8 = K >> 3;                   // 16-byte chunks per row
        for (int idx = tid; idx < 64 * kc8; idx += 256) {
            int n = idx / kc8, c = idx - n * kc8;
            size_t src = (size_t)(n0 + n) * K + c * 8;
            *(uint4*)(sBh + n * BSTR + c * 16) = *(const uint4*)(Bh + src);
            *(uint4*)(sBl + n * BSTR + c * 16) = *(const uint4*)(Bl + src);
        }
    }

    float acc[2][4][4];
#pragma unroll
    for (int mt = 0; mt < 2; mt++)
#pragma unroll
        for (int nt = 0; nt < 4; nt++)
#pragma unroll
            for (int q = 0; q < 4; q++) acc[mt][nt][q] = 0.f;

    for (int kt = 0; kt < K; kt += 32) {
        __syncthreads();
        // ---- stage A tile (128 x 32, hi+lo) ----
#pragma unroll
        for (int l = 0; l < 2; l++) {
            int idx = tid + l * 256;        // 512 x 16B chunks
            int r = idx >> 2, c = idx & 3;
            uint4 vh = make_uint4(0, 0, 0, 0), vl = make_uint4(0, 0, 0, 0);
            if (m0 + r < M) {
                size_t src = (size_t)(m0 + r) * K + kt + c * 8;
                vh = *(const uint4*)(Ah + src);
                vl = *(const uint4*)(Al + src);
            }
            *(uint4*)(sAh + r * ASTR + c * 16) = vh;
            *(uint4*)(sAl + r * ASTR + c * 16) = vl;
        }
        __syncthreads();

#pragma unroll
        for (int kk = 0; kk < 32; kk += 16) {
            int kbA = (kk + 2 * tq) * 2;          // A tile-local k byte offset
            int kbB = (kt + kk + 2 * tq) * 2;     // B global k byte offset
            uint32_t ah[2][4], al[2][4];
#pragma unroll
            for (int mt = 0; mt < 2; mt++) {
                int rb = warp_m * 32 + mt * 16 + group;
                uint32_t o0 = (uint32_t)rb * ASTR + kbA;
                uint32_t o1 = (uint32_t)(rb + 8) * ASTR + kbA;
                ah[mt][0] = *(const uint32_t*)(sAh + o0);
                ah[mt][1] = *(const uint32_t*)(sAh + o1);
                ah[mt][2] = *(const uint32_t*)(sAh + o0 + 16);
                ah[mt][3] = *(const uint32_t*)(sAh + o1 + 16);
                al[mt][0] = *(const uint32_t*)(sAl + o0);
                al[mt][1] = *(const uint32_t*)(sAl + o1);
                al[mt][2] = *(const uint32_t*)(sAl + o0 + 16);
                al[mt][3] = *(const uint32_t*)(sAl + o1 + 16);
            }
            uint32_t bh0[4], bh1[4], bl0[4], bl1[4];
#pragma unroll
            for (int nt = 0; nt < 4; nt++) {
                int n = warp_n * 32 + nt * 8 + group;
                uint32_t o = (uint32_t)n * BSTR + kbB;
                bh0[nt] = *(const uint32_t*)(sBh + o);
                bh1[nt] = *(const uint32_t*)(sBh + o + 16);
                bl0[nt] = *(const uint32_t*)(sBl + o);
                bl1[nt] = *(const uint32_t*)(sBl + o + 16);
            }
#pragma unroll
            for (int mt = 0; mt < 2; mt++)
#pragma unroll
                for (int nt = 0; nt < 4; nt++) {
                    mma16816(acc[mt][nt], ah[mt], bh0[nt], bh1[nt]);   // hi*hi
                    mma16816(acc[mt][nt], al[mt], bh0[nt], bh1[nt]);   // lo*hi
                    mma16816(acc[mt][nt], ah[mt], bl0[nt], bl1[nt]);   // hi*lo
                }
        }
    }

    // ---- epilogue: store C + fused s/d partial dot products ----
    float sp[2][2] = {{0.f, 0.f}, {0.f, 0.f}};
    float dp[2][2] = {{0.f, 0.f}, {0.f, 0.f}};
#pragma unroll
    for (int mt = 0; mt < 2; mt++) {
        int r0 = m0 + warp_m * 32 + mt * 16 + group;
#pragma unroll
        for (int nt = 0; nt < 4; nt++) {
            int col = n0 + warp_n * 32 + nt * 8 + tq * 2;
            float a0 = sAv[col], a1 = sAv[col + 1];
            float d0 = sDv[col], d1 = sDv[col + 1];
            sp[mt][0] += acc[mt][nt][0] * a0 + acc[mt][nt][1] * a1;
            sp[mt][1] += acc[mt][nt][2] * a0 + acc[mt][nt][3] * a1;
            dp[mt][0] += acc[mt][nt][0] * d0 + acc[mt][nt][1] * d1;
            dp[mt][1] += acc[mt][nt][2] * d0 + acc[mt][nt][3] * d1;
            if (r0 < M)
                *(float2*)(C + (size_t)r0 * DHH + col) = make_float2(acc[mt][nt][0], acc[mt][nt][1]);
            if (r0 + 8 < M)
                *(float2*)(C + (size_t)(r0 + 8) * DHH + col) = make_float2(acc[mt][nt][2], acc[mt][nt][3]);
        }
    }
    // reduce across the 4 lanes of a quad (tq = lane & 3)
#pragma unroll
    for (int off = 1; off <= 2; off <<= 1) {
#pragma unroll
        for (int mt = 0; mt < 2; mt++)
#pragma unroll
            for (int rh = 0; rh < 2; rh++) {
                sp[mt][rh] += __shfl_xor_sync(0xffffffffu, sp[mt][rh], off);
                dp[mt][rh] += __shfl_xor_sync(0xffffffffu, dp[mt][rh], off);
            }
    }
    if (tq == 0) {
#pragma unroll
        for (int mt = 0; mt < 2; mt++) {
            int r0 = m0 + warp_m * 32 + mt * 16 + group;
            if (r0 < M)     { atomicAdd(&g_sv[r0], sp[mt][0]);     atomicAdd(&g_dv[r0], dp[mt][0]); }
            if (r0 + 8 < M) { atomicAdd(&g_sv[r0 + 8], sp[mt][1]); atomicAdd(&g_dv[r0 + 8], dp[mt][1]); }
        }
    }
}

// ---------------- per-dst-node softmax + weighted aggregation ---------------
// Also emits bf16 hi/lo of the output (feeds the next layer's GEMM directly).
__global__ __launch_bounds__(256) void k_aggr(const float* __restrict__ bias) {
    int i = blockIdx.x;
    int tid = threadIdx.x;
    int beg = g_rowptr[i];
    int end = g_rowptr[i + 1];
    float di = g_dv[i];

    float m = -1e30f, den = 0.f;
    for (int j = beg + tid; j < end; j += 256) {
        float e = g_sv[g_col[j]] + di;
        e = (e > 0.f) ? e : 0.2f * e;
        if (e > m) { den *= __expf(m - e); m = e; }
        den += __expf(e - m);
    }

    __shared__ float sm_m[256], sm_d[256];
    sm_m[tid] = m; sm_d[tid] = den;
    __syncthreads();
    for (int off = 128; off; off >>= 1) {
        if (tid < off) {
            float m2 = sm_m[tid + off], d2 = sm_d[tid + off];
            float M = fmaxf(m, m2);
            den = den * __expf(m - M) + d2 * __expf(m2 - M);
            m = M;
            sm_m[tid] = m; sm_d[tid] = den;
        }
        __syncthreads();
    }
    float Mtot = sm_m[0];
    float inv = 1.0f / sm_d[0];

    __shared__ float s_alpha[32];
    __shared__ int s_col[32];
    float acc = 0.f;
    for (int base = beg; base < end; base += 32) {
        int cnt = min(32, end - base);
        __syncthreads();
        if (tid < cnt) {
            int c = g_col[base + tid];
            float e = g_sv[c] + di;
            e = (e > 0.f) ? e : 0.2f * e;
            s_alpha[tid] = __expf(e - Mtot) * inv;
            s_col[tid] = c;
        }
        __syncthreads();
        for (int q = 0; q < cnt; q++)
            acc += s_alpha[q] * g_h[(size_t)s_col[q] * DHH + tid];
    }
    size_t idx = (size_t)i * DHH + tid;
    float v = fmaxf(acc + bias[tid], 0.f);   // +b, ReLU
    g_f[idx] = v;
    __nv_bfloat16 h = __float2bfloat16_rn(v);
    g_ah[idx] = h;
    g_al[idx] = __float2bfloat16_rn(v - __bfloat162float(h));
}

// ---------------- pooling ---------------------------------------------------
__global__ void k_pool(const void* __restrict__ batch) {
    __shared__ int sb[64];
    int base = blockIdx.x * 64;
    int tid = threadIdx.x;
    if (tid < 64) sb[tid] = (base + tid < NN) ? ld_idx(batch, base + tid) : -1;
    __syncthreads();
    float acc = 0.f;
    int cur = -1;
    for (int q = 0; q < 64; q++) {
        int g = sb[q];
        if (g < 0) break;
        if (g != cur) {
            if (cur >= 0) atomicAdd(&g_pool[cur * DHH + tid], acc);
            acc = 0.f; cur = g;
        }
        acc += g_f[(size_t)(base + q) * DHH + tid];
    }
    if (cur >= 0) atomicAdd(&g_pool[cur * DHH + tid], acc);
}

// ---------------- final FC --------------------------------------------------
__global__ void k_fc(const float* __restrict__ fcW, const float* __restrict__ fcb,
                     float* __restrict__ out) {
    int g = blockIdx.x;
    int o = threadIdx.x;
    float acc = fcb[o];
    for (int f = 0; f < DHH; f++)
        acc += g_pool[g * DHH + f] * fcW[f * DOUTT + o];
    out[g * DOUTT + o] = acc;
}

// ---------------- launch ----------------------------------------------------
extern "C" void kernel_launch(void* const* d_in, const int* in_sizes, int n_in,
                              void* d_out, int out_size) {
    const float* x = (const float*)d_in[0];
    const void* ei = d_in[1];
    const void* batch = d_in[2];
    const float* W[3]    = {(const float*)d_in[3], (const float*)d_in[7],  (const float*)d_in[11]};
    const float* asrc[3] = {(const float*)d_in[4], (const float*)d_in[8],  (const float*)d_in[12]};
    const float* adst[3] = {(const float*)d_in[5], (const float*)d_in[9],  (const float*)d_in[13]};
    const float* bias[3] = {(const float*)d_in[6], (const float*)d_in[10], (const float*)d_in[14]};
    const float* fcW = (const float*)d_in[15];
    const float* fcb = (const float*)d_in[16];
    float* out = (float*)d_out;

    void *hp = nullptr, *ahp = nullptr, *alp = nullptr, *bhp = nullptr, *blp = nullptr;
    cudaGetSymbolAddress(&hp, g_h);
    cudaGetSymbolAddress(&ahp, g_ah);
    cudaGetSymbolAddress(&alp, g_al);
    cudaGetSymbolAddress(&bhp, g_bh);
    cudaGetSymbolAddress(&blp, g_bl);
    float* hbuf = (float*)hp;

    const int SMEM_MMA = 20480 + 2 * 64 * (2 * DHH + 16) + 2048;   // K=256 worst case
    cudaFuncSetAttribute(k_gemm_mma, cudaFuncAttributeMaxDynamicSharedMemorySize, SMEM_MMA);

    auto launch_gemm = [&](int l, int K) {
        int wthreads = (K * DHH > NN) ? K * DHH : NN;
        k_cvt_w<<<(wthreads + 255) / 256, 256>>>(W[l], K);
        int smem = 20480 + 2 * 64 * (2 * K + 16) + 2048;
        dim3 grid(DHH / 64, (NN + 127) / 128);
        k_gemm_mma<<<grid, 256, smem>>>(
            (const __nv_bfloat16*)ahp, (const __nv_bfloat16*)alp,
            (const __nv_bfloat16*)bhp, (const __nv_bfloat16*)blp,
            hbuf, asrc[l], adst[l], NN, K);
    };

    // Layer-1 GEMM first (no CSR dependency) — puts k_gemm_mma at an early,
    // stable launch index for the ncu capture window.
    k_detect<<<1, 256>>>((const int*)ei);
    k_cvt_a<<<(NN * DINN / 4 + 255) / 256, 256>>>((const float4*)x, NN * DINN / 4);
    launch_gemm(0, DINN);

    // CSR build (needed before the first aggregation)
    k_init_cnt<<<(NN + 255) / 256, 256>>>();
    k_hist<<<(EE + 255) / 256, 256>>>(ei);
    k_chunk_sum<<<NCHUNK, 1024>>>();
    k_scan_chunks<<<1, 1>>>();
    k_local_scan<<<NCHUNK, 1024>>>();
    k_scatter<<<(TOTE + 255) / 256, 256>>>(ei);

    k_aggr<<<NN, 256>>>(bias[0]);

    launch_gemm(1, DHH);
    k_aggr<<<NN, 256>>>(bias[1]);

    launch_gemm(2, DHH);
    k_aggr<<<NN, 256>>>(bias[2]);

    k_pool<<<(NN + 63) / 64, 256>>>(batch);
    k_fc<<<GGG, DOUTT>>>(fcW, fcb, out);
}

// round 8
// speedup vs baseline: 1.1261x; 1.1261x over previous
#include <cuda_runtime.h>
#include <cuda_bf16.h>
#include <cstdint>

#define NN   50000
#define EE   800000
#define DINN 128
#define DHH  256
#define DOUTT 64
#define GGG  64
#define TOTE (EE + NN)
#define NCHUNK 49   // ceil(NN/1024)

// ---------------- scratch (static device globals) ---------------------------
__device__ __align__(16) float g_h[(size_t)NN * DHH];   // GEMM output (per layer)
__device__ __align__(16) float g_f[(size_t)NN * DHH];   // aggregated features
__device__ __align__(16) __nv_bfloat16 g_ah[(size_t)NN * DHH];
__device__ __align__(16) __nv_bfloat16 g_al[(size_t)NN * DHH];
__device__ __align__(16) __nv_bfloat16 g_bh[DHH * DHH];   // Wt hi [256][K]
__device__ __align__(16) __nv_bfloat16 g_bl[DHH * DHH];   // Wt lo [256][K]
__device__ float g_sv[NN];
__device__ float g_dv[NN];
__device__ float g_alpha[TOTE];
__device__ float g_pool[GGG * DHH];
__device__ int   g_cnt[NN];
__device__ int   g_rowptr[NN + 1];
__device__ int   g_cur[NN];
__device__ int   g_col[TOTE];
__device__ int   g_csum[NCHUNK];
__device__ int   g_i32;      // 1 => index tensors are int32, 0 => int64

// ---------------- dtype-agnostic index load ---------------------------------
__device__ __forceinline__ int ld_idx(const void* p, long i) {
    return g_i32 ? ((const int*)p)[i] : (int)((const long long*)p)[i];
}

__global__ void k_detect(const int* __restrict__ ei32) {
    __shared__ int any;
    if (threadIdx.x == 0) any = 0;
    __syncthreads();
    if (ei32[2 * threadIdx.x + 1] != 0) atomicOr(&any, 1);
    __syncthreads();
    if (threadIdx.x == 0) g_i32 = any;
}

// ---------------- CSR build -------------------------------------------------
__global__ void k_init_cnt() {
    int i = blockIdx.x * blockDim.x + threadIdx.x;
    if (i < NN) g_cnt[i] = 1;   // self-loop
}

__global__ void k_hist(const void* __restrict__ ei) {
    int e = blockIdx.x * blockDim.x + threadIdx.x;
    if (e < EE) atomicAdd(&g_cnt[ld_idx(ei, (long)EE + e)], 1);
}

__global__ void k_chunk_sum() {
    __shared__ int sr[1024];
    int tid = threadIdx.x;
    int i = blockIdx.x * 1024 + tid;
    sr[tid] = (i < NN) ? g_cnt[i] : 0;
    __syncthreads();
    for (int off = 512; off; off >>= 1) {
        if (tid < off) sr[tid] += sr[tid + off];
        __syncthreads();
    }
    if (tid == 0) g_csum[blockIdx.x] = sr[0];
}

__global__ void k_scan_chunks() {
    int run = 0;
    for (int c = 0; c < NCHUNK; c++) {
        int t = g_csum[c];
        g_csum[c] = run;
        run += t;
    }
    g_rowptr[NN] = TOTE;
}

__global__ void k_local_scan() {
    __shared__ int ss[1024];
    int tid = threadIdx.x;
    int i = blockIdx.x * 1024 + tid;
    int v = (i < NN) ? g_cnt[i] : 0;
    ss[tid] = v;
    __syncthreads();
    for (int off = 1; off < 1024; off <<= 1) {
        int add = (tid >= off) ? ss[tid - off] : 0;
        __syncthreads();
        ss[tid] += add;
        __syncthreads();
    }
    if (i < NN) {
        int rp = g_csum[blockIdx.x] + ss[tid] - v;   // exclusive
        g_rowptr[i] = rp;
        g_cur[i] = rp;
    }
}

__global__ void k_scatter(const void* __restrict__ ei) {
    int idx = blockIdx.x * blockDim.x + threadIdx.x;
    if (idx < GGG * DHH) g_pool[idx] = 0.f;     // fold pool zeroing in
    if (idx < EE) {
        int src = ld_idx(ei, idx);
        int dst = ld_idx(ei, (long)EE + idx);
        int pos = atomicAdd(&g_cur[dst], 1);
        g_col[pos] = src;
    } else if (idx < TOTE) {
        int i = idx - EE;
        int pos = atomicAdd(&g_cur[i], 1);
        g_col[pos] = i;
    }
}

// ---------------- fp32 -> bf16 hi/lo conversion (layer-1 input only) --------
__global__ void k_cvt_a(const float4* __restrict__ A, int n4) {
    int i = blockIdx.x * blockDim.x + threadIdx.x;
    if (i >= n4) return;
    float4 v = A[i];
    __nv_bfloat16 hx = __float2bfloat16_rn(v.x);
    __nv_bfloat16 hy = __float2bfloat16_rn(v.y);
    __nv_bfloat16 hz = __float2bfloat16_rn(v.z);
    __nv_bfloat16 hw = __float2bfloat16_rn(v.w);
    __nv_bfloat162* oh = (__nv_bfloat162*)g_ah;
    __nv_bfloat162* ol = (__nv_bfloat162*)g_al;
    oh[2 * i]     = __nv_bfloat162(hx, hy);
    oh[2 * i + 1] = __nv_bfloat162(hz, hw);
    ol[2 * i]     = __nv_bfloat162(__float2bfloat16_rn(v.x - __bfloat162float(hx)),
                                   __float2bfloat16_rn(v.y - __bfloat162float(hy)));
    ol[2 * i + 1] = __nv_bfloat162(__float2bfloat16_rn(v.z - __bfloat162float(hz)),
                                   __float2bfloat16_rn(v.w - __bfloat162float(hw)));
}

// W [K, 256] fp32 -> Wt_hi/Wt_lo [256, K] bf16 (transposed, K contiguous).
// Also zeroes g_sv/g_dv for the fused-epilogue atomics of the following GEMM.
__global__ void k_cvt_w(const float* __restrict__ W, int K) {
    int i = blockIdx.x * blockDim.x + threadIdx.x;
    if (i < NN) { g_sv[i] = 0.f; g_dv[i] = 0.f; }
    if (i >= K * DHH) return;
    int n = i / K, k = i - n * K;
    float f = W[(size_t)k * DHH + n];
    __nv_bfloat16 h = __float2bfloat16_rn(f);
    g_bh[i] = h;
    g_bl[i] = __float2bfloat16_rn(f - __bfloat162float(h));
}

// ---------------- HMMA bf16 GEMM: C[M,256] = A[M,K] @ Wt^T ------------------
// mma.sync m16n8k16 bf16, hi/lo 3-pass split. ldmatrix fragment loads (layout
// equivalence to the verified explicit-LDS path proven by R4==R5 outputs).
// Fused epilogue accumulates s_i = h_i.a_src, d_i = h_i.a_dst.
__device__ __forceinline__ uint32_t smem_u32(const void* p) {
    uint32_t a;
    asm("{ .reg .u64 t; cvta.to.shared.u64 t, %1; cvt.u32.u64 %0, t; }" : "=r"(a) : "l"(p));
    return a;
}
__device__ __forceinline__ void ldm_x4(uint32_t* r, uint32_t addr) {
    asm volatile("ldmatrix.sync.aligned.m8n8.x4.shared.b16 {%0,%1,%2,%3}, [%4];"
                 : "=r"(r[0]), "=r"(r[1]), "=r"(r[2]), "=r"(r[3]) : "r"(addr));
}
__device__ __forceinline__ void mma16816(float* c, const uint32_t* a, uint32_t b0, uint32_t b1) {
    asm volatile("mma.sync.aligned.m16n8k16.row.col.f32.bf16.bf16.f32 "
                 "{%0,%1,%2,%3}, {%4,%5,%6,%7}, {%8,%9}, {%0,%1,%2,%3};"
                 : "+f"(c[0]), "+f"(c[1]), "+f"(c[2]), "+f"(c[3])
                 : "r"(a[0]), "r"(a[1]), "r"(a[2]), "r"(a[3]), "r"(b0), "r"(b1));
}

#define ASTR 80   // A row stride bytes (32 bf16 + 8 pad)

__global__ __launch_bounds__(256) void k_gemm_mma(
    const __nv_bfloat16* __restrict__ Ah, const __nv_bfloat16* __restrict__ Al,
    const __nv_bfloat16* __restrict__ Bh, const __nv_bfloat16* __restrict__ Bl,
    float* __restrict__ C, const float* __restrict__ asrc, const float* __restrict__ adst,
    int M, int K)
{
    extern __shared__ char smem[];
    const int BSTR = 2 * K + 16;            // B row stride bytes (odd multiple of 16)
    char* sAh = smem;                       // 128 * 80 = 10240
    char* sAl = smem + 10240;               // 10240
    char* sBh = smem + 20480;               // 64 * BSTR
    char* sBl = sBh + 64 * BSTR;
    float* sAv = (float*)(sBl + 64 * BSTR); // asrc copy [256]
    float* sDv = sAv + DHH;                 // adst copy [256]

    int tid = threadIdx.x;
    int wid = tid >> 5, lane = tid & 31;
    int warp_m = wid >> 1, warp_n = wid & 1;
    int group = lane >> 2, tq = lane & 3;
    int m0 = blockIdx.y * 128;
    int n0 = blockIdx.x * 64;

    sAv[tid] = asrc[tid];
    sDv[tid] = adst[tid];

    // ---- load B slice (64 rows x K, hi+lo) once ----
    {
        int kc8 = K >> 3;                   // 16-byte chunks per row
        for (int idx = tid; idx < 64 * kc8; idx += 256) {
            int n = idx / kc8, c = idx - n * kc8;
            size_t src = (size_t)(n0 + n) * K + c * 8;
            *(uint4*)(sBh + n * BSTR + c * 16) = *(const uint4*)(Bh + src);
            *(uint4*)(sBl + n * BSTR + c * 16) = *(const uint4*)(Bl + src);
        }
    }

    float acc[2][4][4];
#pragma unroll
    for (int mt = 0; mt < 2; mt++)
#pragma unroll
        for (int nt = 0; nt < 4; nt++)
#pragma unroll
            for (int q = 0; q < 4; q++) acc[mt][nt][q] = 0.f;

    // ldmatrix per-thread source rows
    uint32_t sa_h = smem_u32(sAh), sa_l = smem_u32(sAl);
    uint32_t sb_h = smem_u32(sBh), sb_l = smem_u32(sBl);
    int a_row = warp_m * 32 + (lane & 15);
    int a_kh = ((lane >> 4) & 1) * 8;
    int b_n = warp_n * 32 + (lane & 7) + ((lane >> 4) & 1) * 8;
    int b_kh = ((lane >> 3) & 1) * 8;

    for (int kt = 0; kt < K; kt += 32) {
        __syncthreads();
        // ---- stage A tile (128 x 32, hi+lo) ----
#pragma unroll
        for (int l = 0; l < 2; l++) {
            int idx = tid + l * 256;        // 512 x 16B chunks
            int r = idx >> 2, c = idx & 3;
            uint4 vh = make_uint4(0, 0, 0, 0), vl = make_uint4(0, 0, 0, 0);
            if (m0 + r < M) {
                size_t src = (size_t)(m0 + r) * K + kt + c * 8;
                vh = *(const uint4*)(Ah + src);
                vl = *(const uint4*)(Al + src);
            }
            *(uint4*)(sAh + r * ASTR + c * 16) = vh;
            *(uint4*)(sAl + r * ASTR + c * 16) = vl;
        }
        __syncthreads();

#pragma unroll
        for (int kk = 0; kk < 32; kk += 16) {
            uint32_t ah[2][4], al[2][4], bh[2][4], bl[2][4];
#pragma unroll
            for (int mt = 0; mt < 2; mt++) {
                uint32_t off = (uint32_t)(a_row + mt * 16) * ASTR + (kk + a_kh) * 2;
                ldm_x4(ah[mt], sa_h + off);
                ldm_x4(al[mt], sa_l + off);
            }
#pragma unroll
            for (int np = 0; np < 2; np++) {
                uint32_t off = (uint32_t)(b_n + np * 16) * BSTR + (kt + kk + b_kh) * 2;
                ldm_x4(bh[np], sb_h + off);
                ldm_x4(bl[np], sb_l + off);
            }
#pragma unroll
            for (int mt = 0; mt < 2; mt++)
#pragma unroll
                for (int nt = 0; nt < 4; nt++) {
                    uint32_t bregh0 = bh[nt >> 1][(nt & 1) * 2];
                    uint32_t bregh1 = bh[nt >> 1][(nt & 1) * 2 + 1];
                    uint32_t bregl0 = bl[nt >> 1][(nt & 1) * 2];
                    uint32_t bregl1 = bl[nt >> 1][(nt & 1) * 2 + 1];
                    mma16816(acc[mt][nt], ah[mt], bregh0, bregh1);   // hi*hi
                    mma16816(acc[mt][nt], al[mt], bregh0, bregh1);   // lo*hi
                    mma16816(acc[mt][nt], ah[mt], bregl0, bregl1);   // hi*lo
                }
        }
    }

    // ---- epilogue: store C + fused s/d partial dot products ----
    float sp[2][2] = {{0.f, 0.f}, {0.f, 0.f}};
    float dp[2][2] = {{0.f, 0.f}, {0.f, 0.f}};
#pragma unroll
    for (int mt = 0; mt < 2; mt++) {
        int r0 = m0 + warp_m * 32 + mt * 16 + group;
#pragma unroll
        for (int nt = 0; nt < 4; nt++) {
            int col = n0 + warp_n * 32 + nt * 8 + tq * 2;
            float a0 = sAv[col], a1 = sAv[col + 1];
            float d0 = sDv[col], d1 = sDv[col + 1];
            sp[mt][0] += acc[mt][nt][0] * a0 + acc[mt][nt][1] * a1;
            sp[mt][1] += acc[mt][nt][2] * a0 + acc[mt][nt][3] * a1;
            dp[mt][0] += acc[mt][nt][0] * d0 + acc[mt][nt][1] * d1;
            dp[mt][1] += acc[mt][nt][2] * d0 + acc[mt][nt][3] * d1;
            if (r0 < M)
                *(float2*)(C + (size_t)r0 * DHH + col) = make_float2(acc[mt][nt][0], acc[mt][nt][1]);
            if (r0 + 8 < M)
                *(float2*)(C + (size_t)(r0 + 8) * DHH + col) = make_float2(acc[mt][nt][2], acc[mt][nt][3]);
        }
    }
#pragma unroll
    for (int off = 1; off <= 2; off <<= 1) {
#pragma unroll
        for (int mt = 0; mt < 2; mt++)
#pragma unroll
            for (int rh = 0; rh < 2; rh++) {
                sp[mt][rh] += __shfl_xor_sync(0xffffffffu, sp[mt][rh], off);
                dp[mt][rh] += __shfl_xor_sync(0xffffffffu, dp[mt][rh], off);
            }
    }
    if (tq == 0) {
#pragma unroll
        for (int mt = 0; mt < 2; mt++) {
            int r0 = m0 + warp_m * 32 + mt * 16 + group;
            if (r0 < M)     { atomicAdd(&g_sv[r0], sp[mt][0]);     atomicAdd(&g_dv[r0], dp[mt][0]); }
            if (r0 + 8 < M) { atomicAdd(&g_sv[r0 + 8], sp[mt][1]); atomicAdd(&g_dv[r0 + 8], dp[mt][1]); }
        }
    }
}

// ---------------- softmax stats + per-edge alpha (one warp per node) --------
__global__ __launch_bounds__(256) void k_stats() {
    int node = blockIdx.x * 8 + (threadIdx.x >> 5);
    int lane = threadIdx.x & 31;
    if (node >= NN) return;
    int beg = g_rowptr[node];
    int end = g_rowptr[node + 1];
    float di = g_dv[node];

    float m = -1e30f, den = 0.f;
    for (int j = beg + lane; j < end; j += 32) {
        float e = g_sv[g_col[j]] + di;
        e = (e > 0.f) ? e : 0.2f * e;
        if (e > m) { den *= __expf(m - e); m = e; }
        den += __expf(e - m);
    }
#pragma unroll
    for (int off = 16; off; off >>= 1) {
        float m2 = __shfl_xor_sync(0xffffffffu, m, off);
        float d2 = __shfl_xor_sync(0xffffffffu, den, off);
        float M = fmaxf(m, m2);
        den = den * __expf(m - M) + d2 * __expf(m2 - M);
        m = M;
    }
    float inv = 1.0f / den;
    for (int j = beg + lane; j < end; j += 32) {
        float e = g_sv[g_col[j]] + di;
        e = (e > 0.f) ? e : 0.2f * e;
        g_alpha[j] = __expf(e - m) * inv;
    }
}

// ---------------- weighted aggregation (barrier-free streaming) -------------
// one 256-thread block per node; thread tid == feature index. Emits fp32 and
// bf16 hi/lo (feeds the next layer's GEMM directly).
__global__ __launch_bounds__(256) void k_aggr(const float* __restrict__ bias) {
    int i = blockIdx.x;
    int tid = threadIdx.x;
    int beg = g_rowptr[i];
    int end = g_rowptr[i + 1];

    float acc = 0.f;
    int j = beg;
    for (; j + 4 <= end; j += 4) {
        int c0 = g_col[j], c1 = g_col[j + 1], c2 = g_col[j + 2], c3 = g_col[j + 3];
        float a0 = g_alpha[j], a1 = g_alpha[j + 1], a2 = g_alpha[j + 2], a3 = g_alpha[j + 3];
        float f0 = g_h[(size_t)c0 * DHH + tid];
        float f1 = g_h[(size_t)c1 * DHH + tid];
        float f2 = g_h[(size_t)c2 * DHH + tid];
        float f3 = g_h[(size_t)c3 * DHH + tid];
        acc += a0 * f0 + a1 * f1 + a2 * f2 + a3 * f3;
    }
    for (; j < end; j++)
        acc += g_alpha[j] * g_h[(size_t)g_col[j] * DHH + tid];

    size_t idx = (size_t)i * DHH + tid;
    float v = fmaxf(acc + bias[tid], 0.f);   // +b, ReLU
    g_f[idx] = v;
    __nv_bfloat16 h = __float2bfloat16_rn(v);
    g_ah[idx] = h;
    g_al[idx] = __float2bfloat16_rn(v - __bfloat162float(h));
}

// ---------------- pooling ---------------------------------------------------
__global__ void k_pool(const void* __restrict__ batch) {
    __shared__ int sb[64];
    int base = blockIdx.x * 64;
    int tid = threadIdx.x;
    if (tid < 64) sb[tid] = (base + tid < NN) ? ld_idx(batch, base + tid) : -1;
    __syncthreads();
    float acc = 0.f;
    int cur = -1;
    for (int q = 0; q < 64; q++) {
        int g = sb[q];
        if (g < 0) break;
        if (g != cur) {
            if (cur >= 0) atomicAdd(&g_pool[cur * DHH + tid], acc);
            acc = 0.f; cur = g;
        }
        acc += g_f[(size_t)(base + q) * DHH + tid];
    }
    if (cur >= 0) atomicAdd(&g_pool[cur * DHH + tid], acc);
}

// ---------------- final FC --------------------------------------------------
__global__ void k_fc(const float* __restrict__ fcW, const float* __restrict__ fcb,
                     float* __restrict__ out) {
    int g = blockIdx.x;
    int o = threadIdx.x;
    float acc = fcb[o];
    for (int f = 0; f < DHH; f++)
        acc += g_pool[g * DHH + f] * fcW[f * DOUTT + o];
    out[g * DOUTT + o] = acc;
}

// ---------------- launch ----------------------------------------------------
extern "C" void kernel_launch(void* const* d_in, const int* in_sizes, int n_in,
                              void* d_out, int out_size) {
    const float* x = (const float*)d_in[0];
    const void* ei = d_in[1];
    const void* batch = d_in[2];
    const float* W[3]    = {(const float*)d_in[3], (const float*)d_in[7],  (const float*)d_in[11]};
    const float* asrc[3] = {(const float*)d_in[4], (const float*)d_in[8],  (const float*)d_in[12]};
    const float* adst[3] = {(const float*)d_in[5], (const float*)d_in[9],  (const float*)d_in[13]};
    const float* bias[3] = {(const float*)d_in[6], (const float*)d_in[10], (const float*)d_in[14]};
    const float* fcW = (const float*)d_in[15];
    const float* fcb = (const float*)d_in[16];
    float* out = (float*)d_out;

    void *hp = nullptr, *ahp = nullptr, *alp = nullptr, *bhp = nullptr, *blp = nullptr;
    cudaGetSymbolAddress(&hp, g_h);
    cudaGetSymbolAddress(&ahp, g_ah);
    cudaGetSymbolAddress(&alp, g_al);
    cudaGetSymbolAddress(&bhp, g_bh);
    cudaGetSymbolAddress(&blp, g_bl);
    float* hbuf = (float*)hp;

    const int SMEM_MMA = 20480 + 2 * 64 * (2 * DHH + 16) + 2048;   // K=256 worst case
    cudaFuncSetAttribute(k_gemm_mma, cudaFuncAttributeMaxDynamicSharedMemorySize, SMEM_MMA);

    auto launch_gemm = [&](int l, int K) {
        int wthreads = (K * DHH > NN) ? K * DHH : NN;
        k_cvt_w<<<(wthreads + 255) / 256, 256>>>(W[l], K);
        int smem = 20480 + 2 * 64 * (2 * K + 16) + 2048;
        dim3 grid(DHH / 64, (NN + 127) / 128);
        k_gemm_mma<<<grid, 256, smem>>>(
            (const __nv_bfloat16*)ahp, (const __nv_bfloat16*)alp,
            (const __nv_bfloat16*)bhp, (const __nv_bfloat16*)blp,
            hbuf, asrc[l], adst[l], NN, K);
    };

    // Layer-1 GEMM first (no CSR dependency) — stable launch index for ncu.
    k_detect<<<1, 256>>>((const int*)ei);
    k_cvt_a<<<(NN * DINN / 4 + 255) / 256, 256>>>((const float4*)x, NN * DINN / 4);
    launch_gemm(0, DINN);

    // CSR build (needed before the first aggregation)
    k_init_cnt<<<(NN + 255) / 256, 256>>>();
    k_hist<<<(EE + 255) / 256, 256>>>(ei);
    k_chunk_sum<<<NCHUNK, 1024>>>();
    k_scan_chunks<<<1, 1>>>();
    k_local_scan<<<NCHUNK, 1024>>>();
    k_scatter<<<(TOTE + 255) / 256, 256>>>(ei);

    k_stats<<<(NN + 7) / 8, 256>>>();
    k_aggr<<<NN, 256>>>(bias[0]);

    launch_gemm(1, DHH);
    k_stats<<<(NN + 7) / 8, 256>>>();
    k_aggr<<<NN, 256>>>(bias[1]);

    launch_gemm(2, DHH);
    k_stats<<<(NN + 7) / 8, 256>>>();
    k_aggr<<<NN, 256>>>(bias[2]);

    k_pool<<<(NN + 63) / 64, 256>>>(batch);
    k_fc<<<GGG, DOUTT>>>(fcW, fcb, out);
}

// round 9
// speedup vs baseline: 1.2557x; 1.1151x over previous
#include <cuda_runtime.h>
#include <cuda_fp16.h>
#include <cstdint>

#define NN   50000
#define EE   800000
#define DINN 128
#define DHH  256
#define DOUTT 64
#define GGG  64
#define TOTE (EE + NN)
#define NCHUNK 49   // ceil(NN/1024)

// ---------------- scratch (static device globals) ---------------------------
__device__ __align__(16) float g_h[(size_t)NN * DHH];   // GEMM output (per layer)
__device__ __align__(16) float g_f[(size_t)NN * DHH];   // aggregated features
__device__ __align__(16) __half g_ah[(size_t)NN * DHH]; // A hi (fp16)
__device__ __align__(16) __half g_al[(size_t)NN * DHH]; // A lo (fp16)
__device__ __align__(16) __half g_bh[DHH * DHH];        // Wt fp16 [256][K]
__device__ float g_sv[NN];
__device__ float g_dv[NN];
__device__ float g_alpha[TOTE];
__device__ float g_pool[GGG * DHH];
__device__ int   g_cnt[NN];
__device__ int   g_rowptr[NN + 1];
__device__ int   g_cur[NN];
__device__ int   g_col[TOTE];
__device__ int   g_csum[NCHUNK];
__device__ int   g_i32;      // 1 => index tensors are int32, 0 => int64

// ---------------- dtype-agnostic index load ---------------------------------
__device__ __forceinline__ int ld_idx(const void* p, long i) {
    return g_i32 ? ((const int*)p)[i] : (int)((const long long*)p)[i];
}

__global__ void k_detect(const int* __restrict__ ei32) {
    __shared__ int any;
    if (threadIdx.x == 0) any = 0;
    __syncthreads();
    if (ei32[2 * threadIdx.x + 1] != 0) atomicOr(&any, 1);
    __syncthreads();
    if (threadIdx.x == 0) g_i32 = any;
}

// ---------------- CSR build -------------------------------------------------
__global__ void k_init_cnt() {
    int i = blockIdx.x * blockDim.x + threadIdx.x;
    if (i < NN) g_cnt[i] = 1;   // self-loop
}

__global__ void k_hist(const void* __restrict__ ei) {
    int e = blockIdx.x * blockDim.x + threadIdx.x;
    if (e < EE) atomicAdd(&g_cnt[ld_idx(ei, (long)EE + e)], 1);
}

__global__ void k_chunk_sum() {
    __shared__ int sr[1024];
    int tid = threadIdx.x;
    int i = blockIdx.x * 1024 + tid;
    sr[tid] = (i < NN) ? g_cnt[i] : 0;
    __syncthreads();
    for (int off = 512; off; off >>= 1) {
        if (tid < off) sr[tid] += sr[tid + off];
        __syncthreads();
    }
    if (tid == 0) g_csum[blockIdx.x] = sr[0];
}

__global__ void k_scan_chunks() {
    int run = 0;
    for (int c = 0; c < NCHUNK; c++) {
        int t = g_csum[c];
        g_csum[c] = run;
        run += t;
    }
    g_rowptr[NN] = TOTE;
}

__global__ void k_local_scan() {
    __shared__ int ss[1024];
    int tid = threadIdx.x;
    int i = blockIdx.x * 1024 + tid;
    int v = (i < NN) ? g_cnt[i] : 0;
    ss[tid] = v;
    __syncthreads();
    for (int off = 1; off < 1024; off <<= 1) {
        int add = (tid >= off) ? ss[tid - off] : 0;
        __syncthreads();
        ss[tid] += add;
        __syncthreads();
    }
    if (i < NN) {
        int rp = g_csum[blockIdx.x] + ss[tid] - v;   // exclusive
        g_rowptr[i] = rp;
        g_cur[i] = rp;
    }
}

__global__ void k_scatter(const void* __restrict__ ei) {
    int idx = blockIdx.x * blockDim.x + threadIdx.x;
    if (idx < GGG * DHH) g_pool[idx] = 0.f;     // fold pool zeroing in
    if (idx < EE) {
        int src = ld_idx(ei, idx);
        int dst = ld_idx(ei, (long)EE + idx);
        int pos = atomicAdd(&g_cur[dst], 1);
        g_col[pos] = src;
    } else if (idx < TOTE) {
        int i = idx - EE;
        int pos = atomicAdd(&g_cur[i], 1);
        g_col[pos] = i;
    }
}

// ---------------- fp32 -> fp16 hi/lo conversion (layer-1 input only) --------
__global__ void k_cvt_a(const float4* __restrict__ A, int n4) {
    int i = blockIdx.x * blockDim.x + threadIdx.x;
    if (i >= n4) return;
    float4 v = A[i];
    __half hx = __float2half_rn(v.x);
    __half hy = __float2half_rn(v.y);
    __half hz = __float2half_rn(v.z);
    __half hw = __float2half_rn(v.w);
    __half2* oh = (__half2*)g_ah;
    __half2* ol = (__half2*)g_al;
    oh[2 * i]     = __halves2half2(hx, hy);
    oh[2 * i + 1] = __halves2half2(hz, hw);
    ol[2 * i]     = __halves2half2(__float2half_rn(v.x - __half2float(hx)),
                                   __float2half_rn(v.y - __half2float(hy)));
    ol[2 * i + 1] = __halves2half2(__float2half_rn(v.z - __half2float(hz)),
                                   __float2half_rn(v.w - __half2float(hw)));
}

// W [K, 256] fp32 -> Wt fp16 [256, K] via coalesced smem-tile transpose
__global__ void k_cvt_w(const float* __restrict__ W, int K) {
    __shared__ float t[32][33];
    int k0 = blockIdx.x * 32, n0 = blockIdx.y * 32;
    int tx = threadIdx.x, ty = threadIdx.y;   // (32, 8)
#pragma unroll
    for (int i = 0; i < 4; i++)
        t[ty + 8 * i][tx] = W[(size_t)(k0 + ty + 8 * i) * DHH + n0 + tx];
    __syncthreads();
#pragma unroll
    for (int i = 0; i < 4; i++)
        g_bh[(size_t)(n0 + ty + 8 * i) * K + k0 + tx] = __float2half_rn(t[tx][ty + 8 * i]);
}

__global__ void k_zero_sd() {
    int i = blockIdx.x * blockDim.x + threadIdx.x;
    if (i < NN) { g_sv[i] = 0.f; g_dv[i] = 0.f; }
}

// ---------------- HMMA fp16 GEMM: C[M,256] = A[M,K] @ Wt^T ------------------
// mma.sync m16n8k16 fp16, 2-pass hi/lo on A only: (a_hi + a_lo) @ b_fp16.
// CTA tile 128x128, 8 warps (4m x 2n), warp tile 32x64. B resident full-K.
// Fused epilogue accumulates s_i = h_i.a_src, d_i = h_i.a_dst.
__device__ __forceinline__ uint32_t smem_u32(const void* p) {
    uint32_t a;
    asm("{ .reg .u64 t; cvta.to.shared.u64 t, %1; cvt.u32.u64 %0, t; }" : "=r"(a) : "l"(p));
    return a;
}
__device__ __forceinline__ void ldm_x4(uint32_t* r, uint32_t addr) {
    asm volatile("ldmatrix.sync.aligned.m8n8.x4.shared.b16 {%0,%1,%2,%3}, [%4];"
                 : "=r"(r[0]), "=r"(r[1]), "=r"(r[2]), "=r"(r[3]) : "r"(addr));
}
__device__ __forceinline__ void mma16816(float* c, const uint32_t* a, uint32_t b0, uint32_t b1) {
    asm volatile("mma.sync.aligned.m16n8k16.row.col.f32.f16.f16.f32 "
                 "{%0,%1,%2,%3}, {%4,%5,%6,%7}, {%8,%9}, {%0,%1,%2,%3};"
                 : "+f"(c[0]), "+f"(c[1]), "+f"(c[2]), "+f"(c[3])
                 : "r"(a[0]), "r"(a[1]), "r"(a[2]), "r"(a[3]), "r"(b0), "r"(b1));
}

#define ASTR 80   // A row stride bytes (32 fp16 + 8 pad)

__global__ __launch_bounds__(256, 2) void k_gemm_mma(
    const __half* __restrict__ Ah, const __half* __restrict__ Al,
    const __half* __restrict__ Bh,
    float* __restrict__ C, const float* __restrict__ asrc, const float* __restrict__ adst,
    int M, int K)
{
    extern __shared__ char smem[];
    const int BSTR = 2 * K + 16;            // B row stride bytes (odd multiple of 16)
    char* sAh = smem;                       // 128 * 80 = 10240
    char* sAl = smem + 10240;               // 10240
    char* sBh = smem + 20480;               // 128 * BSTR
    float* sAv = (float*)(sBh + 128 * BSTR); // asrc copy [256]
    float* sDv = sAv + DHH;                 // adst copy [256]

    int tid = threadIdx.x;
    int wid = tid >> 5, lane = tid & 31;
    int warp_m = wid >> 1, warp_n = wid & 1;
    int group = lane >> 2, tq = lane & 3;
    int m0 = blockIdx.y * 128;
    int n0 = blockIdx.x * 128;

    sAv[tid] = asrc[tid];
    sDv[tid] = adst[tid];

    // ---- load B slice (128 rows x K, fp16) once ----
    {
        int kc8 = K >> 3;                   // 16-byte chunks per row
        for (int idx = tid; idx < 128 * kc8; idx += 256) {
            int n = idx / kc8, c = idx - n * kc8;
            *(uint4*)(sBh + n * BSTR + c * 16) = *(const uint4*)(Bh + (size_t)(n0 + n) * K + c * 8);
        }
    }

    float acc[2][8][4];
#pragma unroll
    for (int mt = 0; mt < 2; mt++)
#pragma unroll
        for (int nt = 0; nt < 8; nt++)
#pragma unroll
            for (int q = 0; q < 4; q++) acc[mt][nt][q] = 0.f;

    // ldmatrix per-thread source rows
    uint32_t sa_h = smem_u32(sAh), sa_l = smem_u32(sAl);
    uint32_t sb_h = smem_u32(sBh);
    int a_row = warp_m * 32 + (lane & 15);
    int a_kh = ((lane >> 4) & 1) * 8;
    int b_n = warp_n * 64 + (lane & 7) + ((lane >> 4) & 1) * 8;
    int b_kh = ((lane >> 3) & 1) * 8;

    for (int kt = 0; kt < K; kt += 32) {
        __syncthreads();
        // ---- stage A tile (128 x 32, hi+lo) ----
#pragma unroll
        for (int l = 0; l < 2; l++) {
            int idx = tid + l * 256;        // 512 x 16B chunks
            int r = idx >> 2, c = idx & 3;
            uint4 vh = make_uint4(0, 0, 0, 0), vl = make_uint4(0, 0, 0, 0);
            if (m0 + r < M) {
                size_t src = (size_t)(m0 + r) * K + kt + c * 8;
                vh = *(const uint4*)(Ah + src);
                vl = *(const uint4*)(Al + src);
            }
            *(uint4*)(sAh + r * ASTR + c * 16) = vh;
            *(uint4*)(sAl + r * ASTR + c * 16) = vl;
        }
        __syncthreads();

#pragma unroll
        for (int kk = 0; kk < 32; kk += 16) {
            uint32_t ah[2][4], al[2][4], bh[4][4];
#pragma unroll
            for (int mt = 0; mt < 2; mt++) {
                uint32_t off = (uint32_t)(a_row + mt * 16) * ASTR + (kk + a_kh) * 2;
                ldm_x4(ah[mt], sa_h + off);
                ldm_x4(al[mt], sa_l + off);
            }
#pragma unroll
            for (int np = 0; np < 4; np++) {
                uint32_t off = (uint32_t)(b_n + np * 16) * BSTR + (kt + kk + b_kh) * 2;
                ldm_x4(bh[np], sb_h + off);
            }
#pragma unroll
            for (int mt = 0; mt < 2; mt++)
#pragma unroll
                for (int nt = 0; nt < 8; nt++) {
                    uint32_t b0 = bh[nt >> 1][(nt & 1) * 2];
                    uint32_t b1 = bh[nt >> 1][(nt & 1) * 2 + 1];
                    mma16816(acc[mt][nt], ah[mt], b0, b1);   // a_hi * b
                    mma16816(acc[mt][nt], al[mt], b0, b1);   // a_lo * b
                }
        }
    }

    // ---- epilogue: store C + fused s/d partial dot products ----
    float sp[2][2] = {{0.f, 0.f}, {0.f, 0.f}};
    float dp[2][2] = {{0.f, 0.f}, {0.f, 0.f}};
#pragma unroll
    for (int mt = 0; mt < 2; mt++) {
        int r0 = m0 + warp_m * 32 + mt * 16 + group;
#pragma unroll
        for (int nt = 0; nt < 8; nt++) {
            int col = n0 + warp_n * 64 + nt * 8 + tq * 2;
            float a0 = sAv[col], a1 = sAv[col + 1];
            float d0 = sDv[col], d1 = sDv[col + 1];
            sp[mt][0] += acc[mt][nt][0] * a0 + acc[mt][nt][1] * a1;
            sp[mt][1] += acc[mt][nt][2] * a0 + acc[mt][nt][3] * a1;
            dp[mt][0] += acc[mt][nt][0] * d0 + acc[mt][nt][1] * d1;
            dp[mt][1] += acc[mt][nt][2] * d0 + acc[mt][nt][3] * d1;
            if (r0 < M)
                *(float2*)(C + (size_t)r0 * DHH + col) = make_float2(acc[mt][nt][0], acc[mt][nt][1]);
            if (r0 + 8 < M)
                *(float2*)(C + (size_t)(r0 + 8) * DHH + col) = make_float2(acc[mt][nt][2], acc[mt][nt][3]);
        }
    }
#pragma unroll
    for (int off = 1; off <= 2; off <<= 1) {
#pragma unroll
        for (int mt = 0; mt < 2; mt++)
#pragma unroll
            for (int rh = 0; rh < 2; rh++) {
                sp[mt][rh] += __shfl_xor_sync(0xffffffffu, sp[mt][rh], off);
                dp[mt][rh] += __shfl_xor_sync(0xffffffffu, dp[mt][rh], off);
            }
    }
    if (tq == 0) {
#pragma unroll
        for (int mt = 0; mt < 2; mt++) {
            int r0 = m0 + warp_m * 32 + mt * 16 + group;
            if (r0 < M)     { atomicAdd(&g_sv[r0], sp[mt][0]);     atomicAdd(&g_dv[r0], dp[mt][0]); }
            if (r0 + 8 < M) { atomicAdd(&g_sv[r0 + 8], sp[mt][1]); atomicAdd(&g_dv[r0 + 8], dp[mt][1]); }
        }
    }
}

// ---------------- softmax stats + per-edge alpha (one warp per node) --------
__global__ __launch_bounds__(256) void k_stats() {
    int node = blockIdx.x * 8 + (threadIdx.x >> 5);
    int lane = threadIdx.x & 31;
    if (node >= NN) return;
    int beg = g_rowptr[node];
    int end = g_rowptr[node + 1];
    float di = g_dv[node];

    float m = -1e30f, den = 0.f;
    for (int j = beg + lane; j < end; j += 32) {
        float e = g_sv[g_col[j]] + di;
        e = (e > 0.f) ? e : 0.2f * e;
        if (e > m) { den *= __expf(m - e); m = e; }
        den += __expf(e - m);
    }
#pragma unroll
    for (int off = 16; off; off >>= 1) {
        float m2 = __shfl_xor_sync(0xffffffffu, m, off);
        float d2 = __shfl_xor_sync(0xffffffffu, den, off);
        float M = fmaxf(m, m2);
        den = den * __expf(m - M) + d2 * __expf(m2 - M);
        m = M;
    }
    float inv = 1.0f / den;
    for (int j = beg + lane; j < end; j += 32) {
        float e = g_sv[g_col[j]] + di;
        e = (e > 0.f) ? e : 0.2f * e;
        g_alpha[j] = __expf(e - m) * inv;
    }
}

// ---------------- weighted aggregation (barrier-free streaming) -------------
__global__ __launch_bounds__(256) void k_aggr(const float* __restrict__ bias) {
    int i = blockIdx.x;
    int tid = threadIdx.x;
    int beg = g_rowptr[i];
    int end = g_rowptr[i + 1];

    float acc = 0.f;
    int j = beg;
    for (; j + 4 <= end; j += 4) {
        int c0 = g_col[j], c1 = g_col[j + 1], c2 = g_col[j + 2], c3 = g_col[j + 3];
        float a0 = g_alpha[j], a1 = g_alpha[j + 1], a2 = g_alpha[j + 2], a3 = g_alpha[j + 3];
        float f0 = g_h[(size_t)c0 * DHH + tid];
        float f1 = g_h[(size_t)c1 * DHH + tid];
        float f2 = g_h[(size_t)c2 * DHH + tid];
        float f3 = g_h[(size_t)c3 * DHH + tid];
        acc += a0 * f0 + a1 * f1 + a2 * f2 + a3 * f3;
    }
    for (; j < end; j++)
        acc += g_alpha[j] * g_h[(size_t)g_col[j] * DHH + tid];

    size_t idx = (size_t)i * DHH + tid;
    float v = fmaxf(acc + bias[tid], 0.f);   // +b, ReLU
    g_f[idx] = v;
    __half h = __float2half_rn(v);
    g_ah[idx] = h;
    g_al[idx] = __float2half_rn(v - __half2float(h));
}

// ---------------- pooling ---------------------------------------------------
__global__ void k_pool(const void* __restrict__ batch) {
    __shared__ int sb[64];
    int base = blockIdx.x * 64;
    int tid = threadIdx.x;
    if (tid < 64) sb[tid] = (base + tid < NN) ? ld_idx(batch, base + tid) : -1;
    __syncthreads();
    float acc = 0.f;
    int cur = -1;
    for (int q = 0; q < 64; q++) {
        int g = sb[q];
        if (g < 0) break;
        if (g != cur) {
            if (cur >= 0) atomicAdd(&g_pool[cur * DHH + tid], acc);
            acc = 0.f; cur = g;
        }
        acc += g_f[(size_t)(base + q) * DHH + tid];
    }
    if (cur >= 0) atomicAdd(&g_pool[cur * DHH + tid], acc);
}

// ---------------- final FC --------------------------------------------------
__global__ void k_fc(const float* __restrict__ fcW, const float* __restrict__ fcb,
                     float* __restrict__ out) {
    int g = blockIdx.x;
    int o = threadIdx.x;
    float acc = fcb[o];
    for (int f = 0; f < DHH; f++)
        acc += g_pool[g * DHH + f] * fcW[f * DOUTT + o];
    out[g * DOUTT + o] = acc;
}

// ---------------- launch ----------------------------------------------------
extern "C" void kernel_launch(void* const* d_in, const int* in_sizes, int n_in,
                              void* d_out, int out_size) {
    const float* x = (const float*)d_in[0];
    const void* ei = d_in[1];
    const void* batch = d_in[2];
    const float* W[3]    = {(const float*)d_in[3], (const float*)d_in[7],  (const float*)d_in[11]};
    const float* asrc[3] = {(const float*)d_in[4], (const float*)d_in[8],  (const float*)d_in[12]};
    const float* adst[3] = {(const float*)d_in[5], (const float*)d_in[9],  (const float*)d_in[13]};
    const float* bias[3] = {(const float*)d_in[6], (const float*)d_in[10], (const float*)d_in[14]};
    const float* fcW = (const float*)d_in[15];
    const float* fcb = (const float*)d_in[16];
    float* out = (float*)d_out;

    void *hp = nullptr, *ahp = nullptr, *alp = nullptr, *bhp = nullptr;
    cudaGetSymbolAddress(&hp, g_h);
    cudaGetSymbolAddress(&ahp, g_ah);
    cudaGetSymbolAddress(&alp, g_al);
    cudaGetSymbolAddress(&bhp, g_bh);
    float* hbuf = (float*)hp;

    const int SMEM_MMA = 20480 + 128 * (2 * DHH + 16) + 2048;   // K=256: 90112
    cudaFuncSetAttribute(k_gemm_mma, cudaFuncAttributeMaxDynamicSharedMemorySize, SMEM_MMA);

    auto launch_gemm = [&](int l, int K) {
        dim3 tgrid(K / 32, DHH / 32);
        k_cvt_w<<<tgrid, dim3(32, 8)>>>(W[l], K);
        k_zero_sd<<<(NN + 255) / 256, 256>>>();
        int smem = 20480 + 128 * (2 * K + 16) + 2048;
        dim3 grid(DHH / 128, (NN + 127) / 128);
        k_gemm_mma<<<grid, 256, smem>>>(
            (const __half*)ahp, (const __half*)alp, (const __half*)bhp,
            hbuf, asrc[l], adst[l], NN, K);
    };

    // Layer-1 GEMM first (no CSR dependency) — stable launch index for ncu.
    k_detect<<<1, 256>>>((const int*)ei);
    k_cvt_a<<<(NN * DINN / 4 + 255) / 256, 256>>>((const float4*)x, NN * DINN / 4);
    launch_gemm(0, DINN);

    // CSR build (needed before the first aggregation)
    k_init_cnt<<<(NN + 255) / 256, 256>>>();
    k_hist<<<(EE + 255) / 256, 256>>>(ei);
    k_chunk_sum<<<NCHUNK, 1024>>>();
    k_scan_chunks<<<1, 1>>>();
    k_local_scan<<<NCHUNK, 1024>>>();
    k_scatter<<<(TOTE + 255) / 256, 256>>>(ei);

    k_stats<<<(NN + 7) / 8, 256>>>();
    k_aggr<<<NN, 256>>>(bias[0]);

    launch_gemm(1, DHH);
    k_stats<<<(NN + 7) / 8, 256>>>();
    k_aggr<<<NN, 256>>>(bias[1]);

    launch_gemm(2, DHH);
    k_stats<<<(NN + 7) / 8, 256>>>();
    k_aggr<<<NN, 256>>>(bias[2]);

    k_pool<<<(NN + 63) / 64, 256>>>(batch);
    k_fc<<<GGG, DOUTT>>>(fcW, fcb, out);
}

// round 10
// speedup vs baseline: 1.3272x; 1.0570x over previous
#include <cuda_runtime.h>
#include <cuda_fp16.h>
#include <cstdint>

#define NN   50000
#define EE   800000
#define DINN 128
#define DHH  256
#define DOUTT 64
#define GGG  64
#define TOTE (EE + NN)
#define NCHUNK 49   // ceil(NN/1024)

// ---------------- scratch (static device globals) ---------------------------
__device__ __align__(16) __half g_hh[(size_t)NN * DHH]; // GEMM output h (fp16)
__device__ __align__(16) float g_f[(size_t)NN * DHH];   // aggregated (last layer, for pool)
__device__ __align__(16) __half g_ah[(size_t)NN * DHH]; // A hi (fp16)
__device__ __align__(16) __half g_al[(size_t)NN * DHH]; // A lo (fp16)
__device__ __align__(16) __half g_bh[DHH * DHH];        // Wt fp16 [256][K]
__device__ float g_sv[NN];
__device__ float g_dv[NN];
__device__ float g_alpha[TOTE];
__device__ float g_pool[GGG * DHH];
__device__ int   g_cnt[NN];
__device__ int   g_rowptr[NN + 1];
__device__ int   g_cur[NN];
__device__ int   g_col[TOTE];
__device__ int   g_csum[NCHUNK];
__device__ int   g_i32;      // 1 => index tensors are int32, 0 => int64

// ---------------- dtype-agnostic index load ---------------------------------
__device__ __forceinline__ int ld_idx(const void* p, long i) {
    return g_i32 ? ((const int*)p)[i] : (int)((const long long*)p)[i];
}

__global__ void k_detect(const int* __restrict__ ei32) {
    __shared__ int any;
    if (threadIdx.x == 0) any = 0;
    __syncthreads();
    if (ei32[2 * threadIdx.x + 1] != 0) atomicOr(&any, 1);
    __syncthreads();
    if (threadIdx.x == 0) g_i32 = any;
}

// ---------------- CSR build -------------------------------------------------
__global__ void k_init_cnt() {
    int i = blockIdx.x * blockDim.x + threadIdx.x;
    if (i < NN) g_cnt[i] = 1;   // self-loop
}

__global__ void k_hist(const void* __restrict__ ei) {
    int e = blockIdx.x * blockDim.x + threadIdx.x;
    if (e < EE) atomicAdd(&g_cnt[ld_idx(ei, (long)EE + e)], 1);
}

__global__ void k_chunk_sum() {
    __shared__ int sr[1024];
    int tid = threadIdx.x;
    int i = blockIdx.x * 1024 + tid;
    sr[tid] = (i < NN) ? g_cnt[i] : 0;
    __syncthreads();
    for (int off = 512; off; off >>= 1) {
        if (tid < off) sr[tid] += sr[tid + off];
        __syncthreads();
    }
    if (tid == 0) g_csum[blockIdx.x] = sr[0];
}

__global__ void k_scan_chunks() {
    int run = 0;
    for (int c = 0; c < NCHUNK; c++) {
        int t = g_csum[c];
        g_csum[c] = run;
        run += t;
    }
    g_rowptr[NN] = TOTE;
}

__global__ void k_local_scan() {
    __shared__ int ss[1024];
    int tid = threadIdx.x;
    int i = blockIdx.x * 1024 + tid;
    int v = (i < NN) ? g_cnt[i] : 0;
    ss[tid] = v;
    __syncthreads();
    for (int off = 1; off < 1024; off <<= 1) {
        int add = (tid >= off) ? ss[tid - off] : 0;
        __syncthreads();
        ss[tid] += add;
        __syncthreads();
    }
    if (i < NN) {
        int rp = g_csum[blockIdx.x] + ss[tid] - v;   // exclusive
        g_rowptr[i] = rp;
        g_cur[i] = rp;
    }
}

__global__ void k_scatter(const void* __restrict__ ei) {
    int idx = blockIdx.x * blockDim.x + threadIdx.x;
    if (idx < GGG * DHH) g_pool[idx] = 0.f;     // fold pool zeroing in
    if (idx < EE) {
        int src = ld_idx(ei, idx);
        int dst = ld_idx(ei, (long)EE + idx);
        int pos = atomicAdd(&g_cur[dst], 1);
        g_col[pos] = src;
    } else if (idx < TOTE) {
        int i = idx - EE;
        int pos = atomicAdd(&g_cur[i], 1);
        g_col[pos] = i;
    }
}

// ---------------- fp32 -> fp16 hi/lo conversion (layer-1 input only) --------
__global__ void k_cvt_a(const float4* __restrict__ A, int n4) {
    int i = blockIdx.x * blockDim.x + threadIdx.x;
    if (i >= n4) return;
    float4 v = A[i];
    __half hx = __float2half_rn(v.x);
    __half hy = __float2half_rn(v.y);
    __half hz = __float2half_rn(v.z);
    __half hw = __float2half_rn(v.w);
    __half2* oh = (__half2*)g_ah;
    __half2* ol = (__half2*)g_al;
    oh[2 * i]     = __halves2half2(hx, hy);
    oh[2 * i + 1] = __halves2half2(hz, hw);
    ol[2 * i]     = __halves2half2(__float2half_rn(v.x - __half2float(hx)),
                                   __float2half_rn(v.y - __half2float(hy)));
    ol[2 * i + 1] = __halves2half2(__float2half_rn(v.z - __half2float(hz)),
                                   __float2half_rn(v.w - __half2float(hw)));
}

// W [K, 256] fp32 -> Wt fp16 [256, K] via coalesced smem-tile transpose
__global__ void k_cvt_w(const float* __restrict__ W, int K) {
    __shared__ float t[32][33];
    int k0 = blockIdx.x * 32, n0 = blockIdx.y * 32;
    int tx = threadIdx.x, ty = threadIdx.y;   // (32, 8)
#pragma unroll
    for (int i = 0; i < 4; i++)
        t[ty + 8 * i][tx] = W[(size_t)(k0 + ty + 8 * i) * DHH + n0 + tx];
    __syncthreads();
#pragma unroll
    for (int i = 0; i < 4; i++)
        g_bh[(size_t)(n0 + ty + 8 * i) * K + k0 + tx] = __float2half_rn(t[tx][ty + 8 * i]);
}

__global__ void k_zero_sd() {
    int i = blockIdx.x * blockDim.x + threadIdx.x;
    if (i < NN) { g_sv[i] = 0.f; g_dv[i] = 0.f; }
}

// ---------------- HMMA fp16 GEMM: h[M,256] = A[M,K] @ Wt^T ------------------
// mma.sync m16n8k16 fp16, 2-pass hi/lo on A: (a_hi + a_lo) @ b_fp16.
// CTA tile 128x128, 8 warps (4m x 2n), warp tile 32x64. B resident full-K.
// Epilogue: h stored as fp16; s_i / d_i accumulated in fp32 from registers.
__device__ __forceinline__ uint32_t smem_u32(const void* p) {
    uint32_t a;
    asm("{ .reg .u64 t; cvta.to.shared.u64 t, %1; cvt.u32.u64 %0, t; }" : "=r"(a) : "l"(p));
    return a;
}
__device__ __forceinline__ void ldm_x4(uint32_t* r, uint32_t addr) {
    asm volatile("ldmatrix.sync.aligned.m8n8.x4.shared.b16 {%0,%1,%2,%3}, [%4];"
                 : "=r"(r[0]), "=r"(r[1]), "=r"(r[2]), "=r"(r[3]) : "r"(addr));
}
__device__ __forceinline__ void mma16816(float* c, const uint32_t* a, uint32_t b0, uint32_t b1) {
    asm volatile("mma.sync.aligned.m16n8k16.row.col.f32.f16.f16.f32 "
                 "{%0,%1,%2,%3}, {%4,%5,%6,%7}, {%8,%9}, {%0,%1,%2,%3};"
                 : "+f"(c[0]), "+f"(c[1]), "+f"(c[2]), "+f"(c[3])
                 : "r"(a[0]), "r"(a[1]), "r"(a[2]), "r"(a[3]), "r"(b0), "r"(b1));
}

#define ASTR 80   // A row stride bytes (32 fp16 + 8 pad)

__global__ __launch_bounds__(256, 2) void k_gemm_mma(
    const __half* __restrict__ Ah, const __half* __restrict__ Al,
    const __half* __restrict__ Bh,
    __half* __restrict__ C, const float* __restrict__ asrc, const float* __restrict__ adst,
    int M, int K)
{
    extern __shared__ char smem[];
    const int BSTR = 2 * K + 16;            // B row stride bytes (odd multiple of 16)
    char* sAh = smem;                       // 128 * 80 = 10240
    char* sAl = smem + 10240;               // 10240
    char* sBh = smem + 20480;               // 128 * BSTR
    float* sAv = (float*)(sBh + 128 * BSTR); // asrc copy [256]
    float* sDv = sAv + DHH;                 // adst copy [256]

    int tid = threadIdx.x;
    int wid = tid >> 5, lane = tid & 31;
    int warp_m = wid >> 1, warp_n = wid & 1;
    int group = lane >> 2, tq = lane & 3;
    int m0 = blockIdx.y * 128;
    int n0 = blockIdx.x * 128;

    sAv[tid] = asrc[tid];
    sDv[tid] = adst[tid];

    // ---- load B slice (128 rows x K, fp16) once ----
    {
        int kc8 = K >> 3;                   // 16-byte chunks per row
        for (int idx = tid; idx < 128 * kc8; idx += 256) {
            int n = idx / kc8, c = idx - n * kc8;
            *(uint4*)(sBh + n * BSTR + c * 16) = *(const uint4*)(Bh + (size_t)(n0 + n) * K + c * 8);
        }
    }

    float acc[2][8][4];
#pragma unroll
    for (int mt = 0; mt < 2; mt++)
#pragma unroll
        for (int nt = 0; nt < 8; nt++)
#pragma unroll
            for (int q = 0; q < 4; q++) acc[mt][nt][q] = 0.f;

    // ldmatrix per-thread source rows
    uint32_t sa_h = smem_u32(sAh), sa_l = smem_u32(sAl);
    uint32_t sb_h = smem_u32(sBh);
    int a_row = warp_m * 32 + (lane & 15);
    int a_kh = ((lane >> 4) & 1) * 8;
    int b_n = warp_n * 64 + (lane & 7) + ((lane >> 4) & 1) * 8;
    int b_kh = ((lane >> 3) & 1) * 8;

    for (int kt = 0; kt < K; kt += 32) {
        __syncthreads();
        // ---- stage A tile (128 x 32, hi+lo) ----
#pragma unroll
        for (int l = 0; l < 2; l++) {
            int idx = tid + l * 256;        // 512 x 16B chunks
            int r = idx >> 2, c = idx & 3;
            uint4 vh = make_uint4(0, 0, 0, 0), vl = make_uint4(0, 0, 0, 0);
            if (m0 + r < M) {
                size_t src = (size_t)(m0 + r) * K + kt + c * 8;
                vh = *(const uint4*)(Ah + src);
                vl = *(const uint4*)(Al + src);
            }
            *(uint4*)(sAh + r * ASTR + c * 16) = vh;
            *(uint4*)(sAl + r * ASTR + c * 16) = vl;
        }
        __syncthreads();

#pragma unroll
        for (int kk = 0; kk < 32; kk += 16) {
            uint32_t ah[2][4], al[2][4], bh[4][4];
#pragma unroll
            for (int mt = 0; mt < 2; mt++) {
                uint32_t off = (uint32_t)(a_row + mt * 16) * ASTR + (kk + a_kh) * 2;
                ldm_x4(ah[mt], sa_h + off);
                ldm_x4(al[mt], sa_l + off);
            }
#pragma unroll
            for (int np = 0; np < 4; np++) {
                uint32_t off = (uint32_t)(b_n + np * 16) * BSTR + (kt + kk + b_kh) * 2;
                ldm_x4(bh[np], sb_h + off);
            }
#pragma unroll
            for (int mt = 0; mt < 2; mt++)
#pragma unroll
                for (int nt = 0; nt < 8; nt++) {
                    uint32_t b0 = bh[nt >> 1][(nt & 1) * 2];
                    uint32_t b1 = bh[nt >> 1][(nt & 1) * 2 + 1];
                    mma16816(acc[mt][nt], ah[mt], b0, b1);   // a_hi * b
                    mma16816(acc[mt][nt], al[mt], b0, b1);   // a_lo * b
                }
        }
    }

    // ---- epilogue: store h (fp16) + fused fp32 s/d partial dot products ----
    float sp[2][2] = {{0.f, 0.f}, {0.f, 0.f}};
    float dp[2][2] = {{0.f, 0.f}, {0.f, 0.f}};
#pragma unroll
    for (int mt = 0; mt < 2; mt++) {
        int r0 = m0 + warp_m * 32 + mt * 16 + group;
#pragma unroll
        for (int nt = 0; nt < 8; nt++) {
            int col = n0 + warp_n * 64 + nt * 8 + tq * 2;
            float a0 = sAv[col], a1 = sAv[col + 1];
            float d0 = sDv[col], d1 = sDv[col + 1];
            sp[mt][0] += acc[mt][nt][0] * a0 + acc[mt][nt][1] * a1;
            sp[mt][1] += acc[mt][nt][2] * a0 + acc[mt][nt][3] * a1;
            dp[mt][0] += acc[mt][nt][0] * d0 + acc[mt][nt][1] * d1;
            dp[mt][1] += acc[mt][nt][2] * d0 + acc[mt][nt][3] * d1;
            if (r0 < M)
                *(__half2*)(C + (size_t)r0 * DHH + col) =
                    __halves2half2(__float2half_rn(acc[mt][nt][0]), __float2half_rn(acc[mt][nt][1]));
            if (r0 + 8 < M)
                *(__half2*)(C + (size_t)(r0 + 8) * DHH + col) =
                    __halves2half2(__float2half_rn(acc[mt][nt][2]), __float2half_rn(acc[mt][nt][3]));
        }
    }
#pragma unroll
    for (int off = 1; off <= 2; off <<= 1) {
#pragma unroll
        for (int mt = 0; mt < 2; mt++)
#pragma unroll
            for (int rh = 0; rh < 2; rh++) {
                sp[mt][rh] += __shfl_xor_sync(0xffffffffu, sp[mt][rh], off);
                dp[mt][rh] += __shfl_xor_sync(0xffffffffu, dp[mt][rh], off);
            }
    }
    if (tq == 0) {
#pragma unroll
        for (int mt = 0; mt < 2; mt++) {
            int r0 = m0 + warp_m * 32 + mt * 16 + group;
            if (r0 < M)     { atomicAdd(&g_sv[r0], sp[mt][0]);     atomicAdd(&g_dv[r0], dp[mt][0]); }
            if (r0 + 8 < M) { atomicAdd(&g_sv[r0 + 8], sp[mt][1]); atomicAdd(&g_dv[r0 + 8], dp[mt][1]); }
        }
    }
}

// ---------------- softmax stats + per-edge alpha (one warp per node) --------
__global__ __launch_bounds__(256) void k_stats() {
    int node = blockIdx.x * 8 + (threadIdx.x >> 5);
    int lane = threadIdx.x & 31;
    if (node >= NN) return;
    int beg = g_rowptr[node];
    int end = g_rowptr[node + 1];
    float di = g_dv[node];

    float m = -1e30f, den = 0.f;
    for (int j = beg + lane; j < end; j += 32) {
        float e = g_sv[g_col[j]] + di;
        e = (e > 0.f) ? e : 0.2f * e;
        if (e > m) { den *= __expf(m - e); m = e; }
        den += __expf(e - m);
    }
#pragma unroll
    for (int off = 16; off; off >>= 1) {
        float m2 = __shfl_xor_sync(0xffffffffu, m, off);
        float d2 = __shfl_xor_sync(0xffffffffu, den, off);
        float M = fmaxf(m, m2);
        den = den * __expf(m - M) + d2 * __expf(m2 - M);
        m = M;
    }
    float inv = 1.0f / den;
    for (int j = beg + lane; j < end; j += 32) {
        float e = g_sv[g_col[j]] + di;
        e = (e > 0.f) ? e : 0.2f * e;
        g_alpha[j] = __expf(e - m) * inv;
    }
}

// ---------------- weighted aggregation (fp16 gather, barrier-free) ----------
// one 256-thread block per node; thread tid == feature index. Gathers h in
// fp16 (half the L2 traffic); attention weights are full fp32. Emits fp16
// hi/lo for the next GEMM; fp32 g_f only on the last layer (POOL).
template <bool POOL>
__global__ __launch_bounds__(256) void k_aggr(const float* __restrict__ bias) {
    int i = blockIdx.x;
    int tid = threadIdx.x;
    int beg = g_rowptr[i];
    int end = g_rowptr[i + 1];

    float acc = 0.f;
    int j = beg;
    for (; j + 4 <= end; j += 4) {
        int c0 = g_col[j], c1 = g_col[j + 1], c2 = g_col[j + 2], c3 = g_col[j + 3];
        float a0 = g_alpha[j], a1 = g_alpha[j + 1], a2 = g_alpha[j + 2], a3 = g_alpha[j + 3];
        float f0 = __half2float(g_hh[(size_t)c0 * DHH + tid]);
        float f1 = __half2float(g_hh[(size_t)c1 * DHH + tid]);
        float f2 = __half2float(g_hh[(size_t)c2 * DHH + tid]);
        float f3 = __half2float(g_hh[(size_t)c3 * DHH + tid]);
        acc += a0 * f0 + a1 * f1 + a2 * f2 + a3 * f3;
    }
    for (; j < end; j++)
        acc += g_alpha[j] * __half2float(g_hh[(size_t)g_col[j] * DHH + tid]);

    size_t idx = (size_t)i * DHH + tid;
    float v = fmaxf(acc + bias[tid], 0.f);   // +b, ReLU
    if (POOL) g_f[idx] = v;
    __half h = __float2half_rn(v);
    g_ah[idx] = h;
    g_al[idx] = __float2half_rn(v - __half2float(h));
}

// ---------------- pooling ---------------------------------------------------
__global__ void k_pool(const void* __restrict__ batch) {
    __shared__ int sb[64];
    int base = blockIdx.x * 64;
    int tid = threadIdx.x;
    if (tid < 64) sb[tid] = (base + tid < NN) ? ld_idx(batch, base + tid) : -1;
    __syncthreads();
    float acc = 0.f;
    int cur = -1;
    for (int q = 0; q < 64; q++) {
        int g = sb[q];
        if (g < 0) break;
        if (g != cur) {
            if (cur >= 0) atomicAdd(&g_pool[cur * DHH + tid], acc);
            acc = 0.f; cur = g;
        }
        acc += g_f[(size_t)(base + q) * DHH + tid];
    }
    if (cur >= 0) atomicAdd(&g_pool[cur * DHH + tid], acc);
}

// ---------------- final FC --------------------------------------------------
__global__ void k_fc(const float* __restrict__ fcW, const float* __restrict__ fcb,
                     float* __restrict__ out) {
    int g = blockIdx.x;
    int o = threadIdx.x;
    float acc = fcb[o];
    for (int f = 0; f < DHH; f++)
        acc += g_pool[g * DHH + f] * fcW[f * DOUTT + o];
    out[g * DOUTT + o] = acc;
}

// ---------------- launch ----------------------------------------------------
extern "C" void kernel_launch(void* const* d_in, const int* in_sizes, int n_in,
                              void* d_out, int out_size) {
    const float* x = (const float*)d_in[0];
    const void* ei = d_in[1];
    const void* batch = d_in[2];
    const float* W[3]    = {(const float*)d_in[3], (const float*)d_in[7],  (const float*)d_in[11]};
    const float* asrc[3] = {(const float*)d_in[4], (const float*)d_in[8],  (const float*)d_in[12]};
    const float* adst[3] = {(const float*)d_in[5], (const float*)d_in[9],  (const float*)d_in[13]};
    const float* bias[3] = {(const float*)d_in[6], (const float*)d_in[10], (const float*)d_in[14]};
    const float* fcW = (const float*)d_in[15];
    const float* fcb = (const float*)d_in[16];
    float* out = (float*)d_out;

    void *hp = nullptr, *ahp = nullptr, *alp = nullptr, *bhp = nullptr;
    cudaGetSymbolAddress(&hp, g_hh);
    cudaGetSymbolAddress(&ahp, g_ah);
    cudaGetSymbolAddress(&alp, g_al);
    cudaGetSymbolAddress(&bhp, g_bh);
    __half* hbuf = (__half*)hp;

    const int SMEM_MMA = 20480 + 128 * (2 * DHH + 16) + 2048;   // K=256: 90112
    cudaFuncSetAttribute(k_gemm_mma, cudaFuncAttributeMaxDynamicSharedMemorySize, SMEM_MMA);

    auto run_gemm = [&](int l, int K) {
        int smem = 20480 + 128 * (2 * K + 16) + 2048;
        dim3 grid(DHH / 128, (NN + 127) / 128);
        k_gemm_mma<<<grid, 256, smem>>>(
            (const __half*)ahp, (const __half*)alp, (const __half*)bhp,
            hbuf, asrc[l], adst[l], NN, K);
    };

    // Layer-1 prologue ordered so k_gemm_mma is the 4th launch (ncu window).
    k_zero_sd<<<(NN + 255) / 256, 256>>>();                                // 1
    k_cvt_a<<<(NN * DINN / 4 + 255) / 256, 256>>>((const float4*)x, NN * DINN / 4);  // 2
    {
        dim3 tgrid(DINN / 32, DHH / 32);
        k_cvt_w<<<tgrid, dim3(32, 8)>>>(W[0], DINN);                       // 3
    }
    run_gemm(0, DINN);                                                      // 4

    // CSR build (needed before the first aggregation)
    k_detect<<<1, 256>>>((const int*)ei);
    k_init_cnt<<<(NN + 255) / 256, 256>>>();
    k_hist<<<(EE + 255) / 256, 256>>>(ei);
    k_chunk_sum<<<NCHUNK, 1024>>>();
    k_scan_chunks<<<1, 1>>>();
    k_local_scan<<<NCHUNK, 1024>>>();
    k_scatter<<<(TOTE + 255) / 256, 256>>>(ei);

    k_stats<<<(NN + 7) / 8, 256>>>();
    k_aggr<false><<<NN, 256>>>(bias[0]);

    for (int l = 1; l < 3; l++) {
        dim3 tgrid(DHH / 32, DHH / 32);
        k_cvt_w<<<tgrid, dim3(32, 8)>>>(W[l], DHH);
        k_zero_sd<<<(NN + 255) / 256, 256>>>();
        run_gemm(l, DHH);
        k_stats<<<(NN + 7) / 8, 256>>>();
        if (l == 2) k_aggr<true><<<NN, 256>>>(bias[l]);
        else        k_aggr<false><<<NN, 256>>>(bias[l]);
    }

    k_pool<<<(NN + 63) / 64, 256>>>(batch);
    k_fc<<<GGG, DOUTT>>>(fcW, fcb, out);
}

// round 11
// speedup vs baseline: 1.8953x; 1.4280x over previous
#include <cuda_runtime.h>
#include <cuda_fp16.h>
#include <cstdint>

#define NN   50000
#define EE   800000
#define DINN 128
#define DHH  256
#define DOUTT 64
#define GGG  64
#define TOTE (EE + NN)
#define NCHUNK 49   // ceil(NN/1024)

// ---------------- scratch (static device globals) ---------------------------
__device__ __align__(16) __half g_hh[(size_t)NN * DHH]; // GEMM output h (fp16)
__device__ __align__(16) float g_f[(size_t)NN * DHH];   // aggregated (last layer, for pool)
__device__ __align__(16) __half g_ah[(size_t)NN * DHH]; // A hi (fp16)
__device__ __align__(16) __half g_al[(size_t)NN * DHH]; // A lo (fp16)
__device__ __align__(16) __half g_bh[DHH * DHH];        // Wt fp16 [256][K]
__device__ float g_sv[NN];
__device__ float g_dv[NN];
__device__ float g_alpha[TOTE];
__device__ float g_pool[GGG * DHH];
__device__ int   g_cnt[NN];
__device__ int   g_rowptr[NN + 1];
__device__ int   g_cur[NN];
__device__ int   g_col[TOTE];
__device__ int   g_csum[NCHUNK];
__device__ int   g_i32;      // 1 => index tensors are int32, 0 => int64

// ---------------- dtype-agnostic index load ---------------------------------
__device__ __forceinline__ int ld_idx(const void* p, long i) {
    return g_i32 ? ((const int*)p)[i] : (int)((const long long*)p)[i];
}

__global__ void k_detect(const int* __restrict__ ei32) {
    __shared__ int any;
    if (threadIdx.x == 0) any = 0;
    __syncthreads();
    if (ei32[2 * threadIdx.x + 1] != 0) atomicOr(&any, 1);
    __syncthreads();
    if (threadIdx.x == 0) g_i32 = any;
}

// ---------------- CSR build -------------------------------------------------
__global__ void k_init_cnt() {
    int i = blockIdx.x * blockDim.x + threadIdx.x;
    if (i < NN) g_cnt[i] = 1;   // self-loop
}

__global__ void k_hist(const void* __restrict__ ei) {
    int e = blockIdx.x * blockDim.x + threadIdx.x;
    if (e < EE) atomicAdd(&g_cnt[ld_idx(ei, (long)EE + e)], 1);
}

__global__ void k_chunk_sum() {
    __shared__ int sr[1024];
    int tid = threadIdx.x;
    int i = blockIdx.x * 1024 + tid;
    sr[tid] = (i < NN) ? g_cnt[i] : 0;
    __syncthreads();
    for (int off = 512; off; off >>= 1) {
        if (tid < off) sr[tid] += sr[tid + off];
        __syncthreads();
    }
    if (tid == 0) g_csum[blockIdx.x] = sr[0];
}

__global__ void k_scan_chunks() {
    int run = 0;
    for (int c = 0; c < NCHUNK; c++) {
        int t = g_csum[c];
        g_csum[c] = run;
        run += t;
    }
    g_rowptr[NN] = TOTE;
}

__global__ void k_local_scan() {
    __shared__ int ss[1024];
    int tid = threadIdx.x;
    int i = blockIdx.x * 1024 + tid;
    int v = (i < NN) ? g_cnt[i] : 0;
    ss[tid] = v;
    __syncthreads();
    for (int off = 1; off < 1024; off <<= 1) {
        int add = (tid >= off) ? ss[tid - off] : 0;
        __syncthreads();
        ss[tid] += add;
        __syncthreads();
    }
    if (i < NN) {
        int rp = g_csum[blockIdx.x] + ss[tid] - v;   // exclusive
        g_rowptr[i] = rp;
        g_cur[i] = rp;
    }
}

__global__ void k_scatter(const void* __restrict__ ei) {
    int idx = blockIdx.x * blockDim.x + threadIdx.x;
    if (idx < GGG * DHH) g_pool[idx] = 0.f;     // fold pool zeroing in
    if (idx < EE) {
        int src = ld_idx(ei, idx);
        int dst = ld_idx(ei, (long)EE + idx);
        int pos = atomicAdd(&g_cur[dst], 1);
        g_col[pos] = src;
    } else if (idx < TOTE) {
        int i = idx - EE;
        int pos = atomicAdd(&g_cur[i], 1);
        g_col[pos] = i;
    }
}

// ---------------- fp32 -> fp16 hi/lo conversion (layer-1 input only) --------
__global__ void k_cvt_a(const float4* __restrict__ A, int n4) {
    int i = blockIdx.x * blockDim.x + threadIdx.x;
    if (i >= n4) return;
    float4 v = A[i];
    __half hx = __float2half_rn(v.x);
    __half hy = __float2half_rn(v.y);
    __half hz = __float2half_rn(v.z);
    __half hw = __float2half_rn(v.w);
    __half2* oh = (__half2*)g_ah;
    __half2* ol = (__half2*)g_al;
    oh[2 * i]     = __halves2half2(hx, hy);
    oh[2 * i + 1] = __halves2half2(hz, hw);
    ol[2 * i]     = __halves2half2(__float2half_rn(v.x - __half2float(hx)),
                                   __float2half_rn(v.y - __half2float(hy)));
    ol[2 * i + 1] = __halves2half2(__float2half_rn(v.z - __half2float(hz)),
                                   __float2half_rn(v.w - __half2float(hw)));
}

// W [K, 256] fp32 -> Wt fp16 [256, K] via coalesced smem-tile transpose
__global__ void k_cvt_w(const float* __restrict__ W, int K) {
    __shared__ float t[32][33];
    int k0 = blockIdx.x * 32, n0 = blockIdx.y * 32;
    int tx = threadIdx.x, ty = threadIdx.y;   // (32, 8)
#pragma unroll
    for (int i = 0; i < 4; i++)
        t[ty + 8 * i][tx] = W[(size_t)(k0 + ty + 8 * i) * DHH + n0 + tx];
    __syncthreads();
#pragma unroll
    for (int i = 0; i < 4; i++)
        g_bh[(size_t)(n0 + ty + 8 * i) * K + k0 + tx] = __float2half_rn(t[tx][ty + 8 * i]);
}

__global__ void k_zero_sd() {
    int i = blockIdx.x * blockDim.x + threadIdx.x;
    if (i < NN) { g_sv[i] = 0.f; g_dv[i] = 0.f; }
}

// ---------------- HMMA fp16 GEMM: h[M,256] = A[M,K] @ Wt^T ------------------
// mma.sync m16n8k16 fp16, 2-pass hi/lo on A: (a_hi + a_lo) @ b_fp16.
// CTA tile 128x128, 8 warps (4m x 2n). B resident full-K. A tiles staged via
// cp.async with 2-deep double buffering (hides global latency at occ=2).
__device__ __forceinline__ uint32_t smem_u32(const void* p) {
    uint32_t a;
    asm("{ .reg .u64 t; cvta.to.shared.u64 t, %1; cvt.u32.u64 %0, t; }" : "=r"(a) : "l"(p));
    return a;
}
__device__ __forceinline__ void ldm_x4(uint32_t* r, uint32_t addr) {
    asm volatile("ldmatrix.sync.aligned.m8n8.x4.shared.b16 {%0,%1,%2,%3}, [%4];"
                 : "=r"(r[0]), "=r"(r[1]), "=r"(r[2]), "=r"(r[3]) : "r"(addr));
}
__device__ __forceinline__ void mma16816(float* c, const uint32_t* a, uint32_t b0, uint32_t b1) {
    asm volatile("mma.sync.aligned.m16n8k16.row.col.f32.f16.f16.f32 "
                 "{%0,%1,%2,%3}, {%4,%5,%6,%7}, {%8,%9}, {%0,%1,%2,%3};"
                 : "+f"(c[0]), "+f"(c[1]), "+f"(c[2]), "+f"(c[3])
                 : "r"(a[0]), "r"(a[1]), "r"(a[2]), "r"(a[3]), "r"(b0), "r"(b1));
}
__device__ __forceinline__ void cp16(uint32_t dst, const void* src) {
    asm volatile("cp.async.cg.shared.global [%0], [%1], 16;" :: "r"(dst), "l"(src) : "memory");
}
#define CP_COMMIT() asm volatile("cp.async.commit_group;" ::: "memory")
template <int N> __device__ __forceinline__ void cp_wait() {
    asm volatile("cp.async.wait_group %0;" :: "n"(N) : "memory");
}

#define ASTR 80      // A row stride bytes (32 fp16 + 8 pad)
#define ABUF 10240   // one A buffer (128 rows * 80)

__global__ __launch_bounds__(256, 2) void k_gemm_mma(
    const __half* __restrict__ Ah, const __half* __restrict__ Al,
    const __half* __restrict__ Bh,
    __half* __restrict__ C, const float* __restrict__ asrc, const float* __restrict__ adst,
    int M, int K)
{
    extern __shared__ char smem[];
    const int BSTR = 2 * K + 16;              // B row stride bytes (odd multiple of 16)
    // layout: [Ah0|Al0|Ah1|Al1|B|av|dv]
    char* sB = smem + 4 * ABUF;
    float* sAv = (float*)(sB + 128 * BSTR);
    float* sDv = sAv + DHH;

    int tid = threadIdx.x;
    int wid = tid >> 5, lane = tid & 31;
    int warp_m = wid >> 1, warp_n = wid & 1;
    int group = lane >> 2, tq = lane & 3;
    int m0 = blockIdx.y * 128;
    int n0 = blockIdx.x * 128;

    uint32_t sbase = smem_u32(smem);

    // per-thread A staging coords (2 chunks of 16B per buffer-half)
    int st_r[2], st_c[2];
#pragma unroll
    for (int l = 0; l < 2; l++) {
        int idx = tid + l * 256;
        st_r[l] = idx >> 2;
        st_c[l] = idx & 3;
    }

    // issue first A tile (hi+lo) via cp.async
#pragma unroll
    for (int l = 0; l < 2; l++) {
        int grow = m0 + st_r[l];
        if (grow > M - 1) grow = M - 1;     // clamp; OOB rows discarded in epilogue
        size_t src = (size_t)grow * K + st_c[l] * 8;
        uint32_t dst = sbase + st_r[l] * ASTR + st_c[l] * 16;
        cp16(dst, Ah + src);
        cp16(dst + ABUF, Al + src);
    }
    CP_COMMIT();

    sAv[tid] = asrc[tid];
    sDv[tid] = adst[tid];

    // B resident load (overlaps with in-flight cp.async)
    {
        int kc8 = K >> 3;
        for (int idx = tid; idx < 128 * kc8; idx += 256) {
            int n = idx / kc8, c = idx - n * kc8;
            *(uint4*)(sB + n * BSTR + c * 16) = *(const uint4*)(Bh + (size_t)(n0 + n) * K + c * 8);
        }
    }

    float acc[2][8][4];
#pragma unroll
    for (int mt = 0; mt < 2; mt++)
#pragma unroll
        for (int nt = 0; nt < 8; nt++)
#pragma unroll
            for (int q = 0; q < 4; q++) acc[mt][nt][q] = 0.f;

    uint32_t sb_h = smem_u32(sB);
    int a_row = warp_m * 32 + (lane & 15);
    int a_kh = ((lane >> 4) & 1) * 8;
    int b_n = warp_n * 64 + (lane & 7) + ((lane >> 4) & 1) * 8;
    int b_kh = ((lane >> 3) & 1) * 8;

    const int NCH = K >> 5;
    for (int c = 0; c < NCH; c++) {
        if (c + 1 < NCH) {
            uint32_t bufo = (uint32_t)((c + 1) & 1) * 2 * ABUF;
#pragma unroll
            for (int l = 0; l < 2; l++) {
                int grow = m0 + st_r[l];
                if (grow > M - 1) grow = M - 1;
                size_t src = (size_t)grow * K + (c + 1) * 32 + st_c[l] * 8;
                uint32_t dst = sbase + bufo + st_r[l] * ASTR + st_c[l] * 16;
                cp16(dst, Ah + src);
                cp16(dst + ABUF, Al + src);
            }
            CP_COMMIT();
            cp_wait<1>();
        } else {
            cp_wait<0>();
        }
        __syncthreads();

        uint32_t cbuf = (uint32_t)(c & 1) * 2 * ABUF;
        uint32_t sa_h = sbase + cbuf;
        uint32_t sa_l = sa_h + ABUF;
        int kt = c * 32;

#pragma unroll
        for (int kk = 0; kk < 32; kk += 16) {
            uint32_t ah[2][4], al[2][4], bh[4][4];
#pragma unroll
            for (int mt = 0; mt < 2; mt++) {
                uint32_t off = (uint32_t)(a_row + mt * 16) * ASTR + (kk + a_kh) * 2;
                ldm_x4(ah[mt], sa_h + off);
                ldm_x4(al[mt], sa_l + off);
            }
#pragma unroll
            for (int np = 0; np < 4; np++) {
                uint32_t off = (uint32_t)(b_n + np * 16) * BSTR + (kt + kk + b_kh) * 2;
                ldm_x4(bh[np], sb_h + off);
            }
#pragma unroll
            for (int mt = 0; mt < 2; mt++)
#pragma unroll
                for (int nt = 0; nt < 8; nt++) {
                    uint32_t b0 = bh[nt >> 1][(nt & 1) * 2];
                    uint32_t b1 = bh[nt >> 1][(nt & 1) * 2 + 1];
                    mma16816(acc[mt][nt], ah[mt], b0, b1);   // a_hi * b
                    mma16816(acc[mt][nt], al[mt], b0, b1);   // a_lo * b
                }
        }
        __syncthreads();   // all warps done reading before this buffer is re-staged
    }

    // ---- epilogue: store h (fp16) + fused fp32 s/d partial dot products ----
    float sp[2][2] = {{0.f, 0.f}, {0.f, 0.f}};
    float dp[2][2] = {{0.f, 0.f}, {0.f, 0.f}};
#pragma unroll
    for (int mt = 0; mt < 2; mt++) {
        int r0 = m0 + warp_m * 32 + mt * 16 + group;
#pragma unroll
        for (int nt = 0; nt < 8; nt++) {
            int col = n0 + warp_n * 64 + nt * 8 + tq * 2;
            float a0 = sAv[col], a1 = sAv[col + 1];
            float d0 = sDv[col], d1 = sDv[col + 1];
            sp[mt][0] += acc[mt][nt][0] * a0 + acc[mt][nt][1] * a1;
            sp[mt][1] += acc[mt][nt][2] * a0 + acc[mt][nt][3] * a1;
            dp[mt][0] += acc[mt][nt][0] * d0 + acc[mt][nt][1] * d1;
            dp[mt][1] += acc[mt][nt][2] * d0 + acc[mt][nt][3] * d1;
            if (r0 < M)
                *(__half2*)(C + (size_t)r0 * DHH + col) =
                    __halves2half2(__float2half_rn(acc[mt][nt][0]), __float2half_rn(acc[mt][nt][1]));
            if (r0 + 8 < M)
                *(__half2*)(C + (size_t)(r0 + 8) * DHH + col) =
                    __halves2half2(__float2half_rn(acc[mt][nt][2]), __float2half_rn(acc[mt][nt][3]));
        }
    }
#pragma unroll
    for (int off = 1; off <= 2; off <<= 1) {
#pragma unroll
        for (int mt = 0; mt < 2; mt++)
#pragma unroll
            for (int rh = 0; rh < 2; rh++) {
                sp[mt][rh] += __shfl_xor_sync(0xffffffffu, sp[mt][rh], off);
                dp[mt][rh] += __shfl_xor_sync(0xffffffffu, dp[mt][rh], off);
            }
    }
    if (tq == 0) {
#pragma unroll
        for (int mt = 0; mt < 2; mt++) {
            int r0 = m0 + warp_m * 32 + mt * 16 + group;
            if (r0 < M)     { atomicAdd(&g_sv[r0], sp[mt][0]);     atomicAdd(&g_dv[r0], dp[mt][0]); }
            if (r0 + 8 < M) { atomicAdd(&g_sv[r0 + 8], sp[mt][1]); atomicAdd(&g_dv[r0 + 8], dp[mt][1]); }
        }
    }
}

// ---------------- softmax stats + per-edge alpha (one warp per node) --------
__global__ __launch_bounds__(256) void k_stats() {
    int node = blockIdx.x * 8 + (threadIdx.x >> 5);
    int lane = threadIdx.x & 31;
    if (node >= NN) return;
    int beg = g_rowptr[node];
    int end = g_rowptr[node + 1];
    float di = g_dv[node];

    float m = -1e30f, den = 0.f;
    for (int j = beg + lane; j < end; j += 32) {
        float e = g_sv[g_col[j]] + di;
        e = (e > 0.f) ? e : 0.2f * e;
        if (e > m) { den *= __expf(m - e); m = e; }
        den += __expf(e - m);
    }
#pragma unroll
    for (int off = 16; off; off >>= 1) {
        float m2 = __shfl_xor_sync(0xffffffffu, m, off);
        float d2 = __shfl_xor_sync(0xffffffffu, den, off);
        float M = fmaxf(m, m2);
        den = den * __expf(m - M) + d2 * __expf(m2 - M);
        m = M;
    }
    float inv = 1.0f / den;
    for (int j = beg + lane; j < end; j += 32) {
        float e = g_sv[g_col[j]] + di;
        e = (e > 0.f) ? e : 0.2f * e;
        g_alpha[j] = __expf(e - m) * inv;
    }
}

// ---------------- weighted aggregation (half2 gather, barrier-free) ---------
// one 128-thread block per node; thread tid owns features 2*tid, 2*tid+1.
template <bool POOL>
__global__ __launch_bounds__(128) void k_aggr(const float* __restrict__ bias) {
    int i = blockIdx.x;
    int tid = threadIdx.x;
    int beg = g_rowptr[i];
    int end = g_rowptr[i + 1];
    int f2 = tid * 2;

    float ax = 0.f, ay = 0.f;
    int j = beg;
    for (; j + 4 <= end; j += 4) {
        int c0 = g_col[j], c1 = g_col[j + 1], c2 = g_col[j + 2], c3 = g_col[j + 3];
        float a0 = g_alpha[j], a1 = g_alpha[j + 1], a2 = g_alpha[j + 2], a3 = g_alpha[j + 3];
        float2 f0 = __half22float2(*(const __half2*)(g_hh + (size_t)c0 * DHH + f2));
        float2 f1 = __half22float2(*(const __half2*)(g_hh + (size_t)c1 * DHH + f2));
        float2 fq2 = __half22float2(*(const __half2*)(g_hh + (size_t)c2 * DHH + f2));
        float2 f3 = __half22float2(*(const __half2*)(g_hh + (size_t)c3 * DHH + f2));
        ax += a0 * f0.x + a1 * f1.x + a2 * fq2.x + a3 * f3.x;
        ay += a0 * f0.y + a1 * f1.y + a2 * fq2.y + a3 * f3.y;
    }
    for (; j < end; j++) {
        float a = g_alpha[j];
        float2 f = __half22float2(*(const __half2*)(g_hh + (size_t)g_col[j] * DHH + f2));
        ax += a * f.x;
        ay += a * f.y;
    }

    float2 b = *(const float2*)(bias + f2);
    float vx = fmaxf(ax + b.x, 0.f);
    float vy = fmaxf(ay + b.y, 0.f);
    size_t idx = (size_t)i * DHH + f2;
    if (POOL) *(float2*)(g_f + idx) = make_float2(vx, vy);
    __half hx = __float2half_rn(vx), hy = __float2half_rn(vy);
    *(__half2*)(g_ah + idx) = __halves2half2(hx, hy);
    *(__half2*)(g_al + idx) = __halves2half2(__float2half_rn(vx - __half2float(hx)),
                                             __float2half_rn(vy - __half2float(hy)));
}

// ---------------- pooling ---------------------------------------------------
__global__ void k_pool(const void* __restrict__ batch) {
    __shared__ int sb[64];
    int base = blockIdx.x * 64;
    int tid = threadIdx.x;
    if (tid < 64) sb[tid] = (base + tid < NN) ? ld_idx(batch, base + tid) : -1;
    __syncthreads();
    float acc = 0.f;
    int cur = -1;
    for (int q = 0; q < 64; q++) {
        int g = sb[q];
        if (g < 0) break;
        if (g != cur) {
            if (cur >= 0) atomicAdd(&g_pool[cur * DHH + tid], acc);
            acc = 0.f; cur = g;
        }
        acc += g_f[(size_t)(base + q) * DHH + tid];
    }
    if (cur >= 0) atomicAdd(&g_pool[cur * DHH + tid], acc);
}

// ---------------- final FC --------------------------------------------------
__global__ void k_fc(const float* __restrict__ fcW, const float* __restrict__ fcb,
                     float* __restrict__ out) {
    int g = blockIdx.x;
    int o = threadIdx.x;
    float acc = fcb[o];
    for (int f = 0; f < DHH; f++)
        acc += g_pool[g * DHH + f] * fcW[f * DOUTT + o];
    out[g * DOUTT + o] = acc;
}

// ---------------- launch ----------------------------------------------------
extern "C" void kernel_launch(void* const* d_in, const int* in_sizes, int n_in,
                              void* d_out, int out_size) {
    const float* x = (const float*)d_in[0];
    const void* ei = d_in[1];
    const void* batch = d_in[2];
    const float* W[3]    = {(const float*)d_in[3], (const float*)d_in[7],  (const float*)d_in[11]};
    const float* asrc[3] = {(const float*)d_in[4], (const float*)d_in[8],  (const float*)d_in[12]};
    const float* adst[3] = {(const float*)d_in[5], (const float*)d_in[9],  (const float*)d_in[13]};
    const float* bias[3] = {(const float*)d_in[6], (const float*)d_in[10], (const float*)d_in[14]};
    const float* fcW = (const float*)d_in[15];
    const float* fcb = (const float*)d_in[16];
    float* out = (float*)d_out;

    void *hp = nullptr, *ahp = nullptr, *alp = nullptr, *bhp = nullptr;
    cudaGetSymbolAddress(&hp, g_hh);
    cudaGetSymbolAddress(&ahp, g_ah);
    cudaGetSymbolAddress(&alp, g_al);
    cudaGetSymbolAddress(&bhp, g_bh);
    __half* hbuf = (__half*)hp;

    const int SMEM_MMA = 4 * ABUF + 128 * (2 * DHH + 16) + 2048;   // K=256: 110592
    cudaFuncSetAttribute(k_gemm_mma, cudaFuncAttributeMaxDynamicSharedMemorySize, SMEM_MMA);

    auto run_gemm = [&](int l, int K) {
        int smem = 4 * ABUF + 128 * (2 * K + 16) + 2048;
        dim3 grid(DHH / 128, (NN + 127) / 128);
        k_gemm_mma<<<grid, 256, smem>>>(
            (const __half*)ahp, (const __half*)alp, (const __half*)bhp,
            hbuf, asrc[l], adst[l], NN, K);
    };

    // Layer-1 prologue ordered so k_gemm_mma is the 4th launch (ncu window).
    k_zero_sd<<<(NN + 255) / 256, 256>>>();                                // 1
    k_cvt_a<<<(NN * DINN / 4 + 255) / 256, 256>>>((const float4*)x, NN * DINN / 4);  // 2
    {
        dim3 tgrid(DINN / 32, DHH / 32);
        k_cvt_w<<<tgrid, dim3(32, 8)>>>(W[0], DINN);                       // 3
    }
    run_gemm(0, DINN);                                                      // 4

    // CSR build (needed before the first aggregation)
    k_detect<<<1, 256>>>((const int*)ei);
    k_init_cnt<<<(NN + 255) / 256, 256>>>();
    k_hist<<<(EE + 255) / 256, 256>>>(ei);
    k_chunk_sum<<<NCHUNK, 1024>>>();
    k_scan_chunks<<<1, 1>>>();
    k_local_scan<<<NCHUNK, 1024>>>();
    k_scatter<<<(TOTE + 255) / 256, 256>>>(ei);

    k_stats<<<(NN + 7) / 8, 256>>>();
    k_aggr<false><<<NN, 128>>>(bias[0]);

    for (int l = 1; l < 3; l++) {
        dim3 tgrid(DHH / 32, DHH / 32);
        k_cvt_w<<<tgrid, dim3(32, 8)>>>(W[l], DHH);
        k_zero_sd<<<(NN + 255) / 256, 256>>>();
        run_gemm(l, DHH);
        k_stats<<<(NN + 7) / 8, 256>>>();
        if (l == 2) k_aggr<true><<<NN, 128>>>(bias[l]);
        else        k_aggr<false><<<NN, 128>>>(bias[l]);
    }

    k_pool<<<(NN + 63) / 64, 256>>>(batch);
    k_fc<<<GGG, DOUTT>>>(fcW, fcb, out);
}